// round 2
// baseline (speedup 1.0000x reference)
#include <cuda_runtime.h>
#include <math.h>
#include <stdint.h>

#define NN 100000
#define NE 1200000
#define GC 64
#define RBF 32
#define NL 4
#define NF 92
#define NTYPES 100

// ---------------- scratch (static device globals; no runtime allocation) ----------------
__device__ float g_edge_attr[(size_t)NE * RBF];   // 153.6 MB
__device__ float g_proj[(size_t)NN * 4 * GC];     // 102.4 MB  [n][Af|As|Bf|Bs]
__device__ float g_agg[(size_t)NN * GC];          // 25.6 MB
__device__ float g_x[(size_t)NN * GC];            // 25.6 MB
__device__ float g_deg[NN];
__device__ float g_invdeg[NN];
__device__ float g_table[NTYPES * GC];
__device__ float g_stats[2 * GC];

// ---------------- edge prep: distances -> expnorm RBF * cosine cutoff; degree count ----------------
__global__ void edge_prep_kernel(const float* __restrict__ pos,
                                 const int* __restrict__ src,
                                 const int* __restrict__ dst,
                                 const float* __restrict__ means,
                                 const float* __restrict__ betas)
{
    int lane = threadIdx.x & 31;
    int warp = (blockIdx.x * blockDim.x + threadIdx.x) >> 5;
    int nwarps = (gridDim.x * blockDim.x) >> 5;
    float mean = means[lane];
    float beta = betas[lane];
    for (int e = warp; e < NE; e += nwarps) {
        int s = src[e], d = dst[e];
        float dx = pos[s * 3 + 0] - pos[d * 3 + 0];
        float dy = pos[s * 3 + 1] - pos[d * 3 + 1];
        float dz = pos[s * 3 + 2] - pos[d * 3 + 2];
        float dist = sqrtf(dx * dx + dy * dy + dz * dz + 1e-12f);
        float cut = (dist < 5.0f) ? 0.5f * (__cosf(dist * 0.62831853071795f) + 1.0f) : 0.0f;
        float expd = __expf(-dist);          // alpha = 5/5 = 1
        float t = expd - mean;
        g_edge_attr[(size_t)e * RBF + lane] = cut * __expf(-beta * t * t);
        if (lane == 0) atomicAdd(&g_deg[d], 1.0f);
    }
}

__global__ void inv_deg_kernel()
{
    int n = blockIdx.x * blockDim.x + threadIdx.x;
    if (n < NN) {
        float d = g_deg[n];
        g_invdeg[n] = (d > 0.0f) ? (1.0f / d) : 0.0f;
    }
}

// ---------------- embedding + pre-layer: only 100 atom types -> build a table ----------------
__global__ void pre_table_kernel(const float* __restrict__ emb,
                                 const float* __restrict__ pre_W,
                                 const float* __restrict__ pre_b)
{
    int t = blockIdx.x;       // atom type
    int c = threadIdx.x;      // channel
    float acc = pre_b[c];
    #pragma unroll 4
    for (int f = 0; f < NF; f++)
        acc = fmaf(emb[t * NF + f], pre_W[f * GC + c], acc);
    g_table[t * GC + c] = fmaxf(acc, 0.0f);
}

__global__ void gather_x_kernel(const int* __restrict__ atom)
{
    for (int i = blockIdx.x * blockDim.x + threadIdx.x; i < NN * GC;
         i += gridDim.x * blockDim.x) {
        int n = i >> 6;
        g_x[i] = g_table[atom[n] * GC + (i & 63)];
    }
}

// ---------------- per-node projections: [Af|As|Bf|Bs] = x @ {Wf[0:64],Ws[0:64],Wf[64:128],Ws[64:128]} ----------------
#define PROJ_SMEM ((4 * 64 * 64 + 16 * 64) * 4)
__global__ __launch_bounds__(256) void proj_kernel(const float* __restrict__ Wf_l,
                                                   const float* __restrict__ Ws_l)
{
    extern __shared__ float sm[];
    float* wsm = sm;                 // [4][64][64]
    float* xs  = sm + 4 * 64 * 64;   // [16][64]

    for (int i = threadIdx.x; i < 64 * 64; i += blockDim.x) {
        int k = i >> 6, c = i & 63;
        wsm[0 * 4096 + i] = Wf_l[k * GC + c];            // Af: Wf rows 0..63   (x_dst)
        wsm[1 * 4096 + i] = Ws_l[k * GC + c];            // As
        wsm[2 * 4096 + i] = Wf_l[(64 + k) * GC + c];     // Bf: Wf rows 64..127 (x_src)
        wsm[3 * 4096 + i] = Ws_l[(64 + k) * GC + c];     // Bs
    }

    int c = threadIdx.x & 63;
    int g = threadIdx.x >> 6;  // 0..3, owns 4 nodes of the 16-node tile

    for (int nb = blockIdx.x * 16; nb < NN; nb += gridDim.x * 16) {
        __syncthreads();
        for (int i = threadIdx.x; i < 16 * 64; i += blockDim.x) {
            int nn = nb + (i >> 6);
            xs[i] = (nn < NN) ? g_x[(size_t)nn * GC + (i & 63)] : 0.0f;
        }
        __syncthreads();

        float acc[4][4] = {};
        #pragma unroll 16
        for (int k = 0; k < 64; k++) {
            float w0 = wsm[k * 64 + c];
            float w1 = wsm[4096 + k * 64 + c];
            float w2 = wsm[8192 + k * 64 + c];
            float w3 = wsm[12288 + k * 64 + c];
            #pragma unroll
            for (int j = 0; j < 4; j++) {
                float xv = xs[(g * 4 + j) * 64 + k];
                acc[j][0] = fmaf(xv, w0, acc[j][0]);
                acc[j][1] = fmaf(xv, w1, acc[j][1]);
                acc[j][2] = fmaf(xv, w2, acc[j][2]);
                acc[j][3] = fmaf(xv, w3, acc[j][3]);
            }
        }
        #pragma unroll
        for (int j = 0; j < 4; j++) {
            int n = nb + g * 4 + j;
            if (n < NN) {
                float* p = &g_proj[(size_t)n * 256];
                p[c]       = acc[j][0];
                p[64 + c]  = acc[j][1];
                p[128 + c] = acc[j][2];
                p[192 + c] = acc[j][3];
            }
        }
    }
}

// ---------------- edge messages + scatter: msg = sigmoid(Af+Bf+Ef+bf)*softplus(As+Bs+Es+bs) ----------------
__global__ __launch_bounds__(256, 2) void msg_kernel(const int* __restrict__ src,
                                                     const int* __restrict__ dst,
                                                     const float* __restrict__ Wfe,  // Wf rows 128..159
                                                     const float* __restrict__ Wse,  // Ws rows 128..159
                                                     const float* __restrict__ bfv,
                                                     const float* __restrict__ bsv)
{
    __shared__ __align__(16) float ea_s[4][RBF];
    int c = threadIdx.x & 63;
    int g = threadIdx.x >> 6;   // 4 edges per block-iteration

    float wf[RBF], ws[RBF];
    #pragma unroll
    for (int k = 0; k < RBF; k++) {
        wf[k] = Wfe[k * GC + c];
        ws[k] = Wse[k * GC + c];
    }
    float bfc = bfv[c], bsc = bsv[c];

    for (int base = blockIdx.x * 4; base < NE; base += gridDim.x * 4) {
        int e = base + g;
        bool valid = (e < NE);
        int d_ = 0;
        float gAf = 0.f, gAs = 0.f, gBf = 0.f, gBs = 0.f;
        if (valid) {
            int s_ = src[e];
            d_ = dst[e];
            const float* pd = &g_proj[(size_t)d_ * 256];
            const float* ps = &g_proj[(size_t)s_ * 256];
            gAf = pd[c];
            gAs = pd[64 + c];
            gBf = ps[128 + c];
            gBs = ps[192 + c];
            if (c < RBF) ea_s[g][c] = g_edge_attr[(size_t)e * RBF + c];
        }
        __syncthreads();
        if (valid) {
            float f  = bfc + gAf + gBf;
            float sv = bsc + gAs + gBs;
            const float4* ea4 = (const float4*)ea_s[g];
            #pragma unroll
            for (int k4 = 0; k4 < RBF / 4; k4++) {
                float4 a = ea4[k4];
                f  = fmaf(a.x, wf[4 * k4 + 0], f);
                f  = fmaf(a.y, wf[4 * k4 + 1], f);
                f  = fmaf(a.z, wf[4 * k4 + 2], f);
                f  = fmaf(a.w, wf[4 * k4 + 3], f);
                sv = fmaf(a.x, ws[4 * k4 + 0], sv);
                sv = fmaf(a.y, ws[4 * k4 + 1], sv);
                sv = fmaf(a.z, ws[4 * k4 + 2], sv);
                sv = fmaf(a.w, ws[4 * k4 + 3], sv);
            }
            // sigmoid
            float sig = __fdividef(1.0f, 1.0f + __expf(-f));
            // softplus (overflow-safe)
            float sp = (sv > 20.0f) ? sv : __logf(1.0f + __expf(sv));
            float m = sig * sp;
            atomicAdd(&g_agg[(size_t)d_ * GC + c], m);
        }
        __syncthreads();   // protect ea_s before next iteration's writes
    }
}

// ---------------- x += agg*inv_deg; accumulate BN stats ----------------
__global__ __launch_bounds__(256) void update_stats_kernel()
{
    __shared__ float ssum[256], ssq[256];
    int c = threadIdx.x & 63;
    int g = threadIdx.x >> 6;
    float lsum = 0.f, lsq = 0.f;
    for (int i = blockIdx.x * blockDim.x + threadIdx.x; i < NN * GC;
         i += gridDim.x * blockDim.x) {
        int n = i >> 6;
        float v = g_x[i] + g_agg[i] * g_invdeg[n];
        g_x[i] = v;
        lsum += v;
        lsq = fmaf(v, v, lsq);
    }
    ssum[threadIdx.x] = lsum;
    ssq[threadIdx.x] = lsq;
    __syncthreads();
    if (g == 0) {
        float a = ssum[c] + ssum[64 + c] + ssum[128 + c] + ssum[192 + c];
        float b = ssq[c] + ssq[64 + c] + ssq[128 + c] + ssq[192 + c];
        atomicAdd(&g_stats[c], a);
        atomicAdd(&g_stats[GC + c], b);
    }
}

// ---------------- BN normalize (writes g_x, or d_out on last layer) ----------------
__global__ __launch_bounds__(256) void bn_norm_kernel(const float* __restrict__ gamma,
                                                      const float* __restrict__ beta,
                                                      float* __restrict__ out)
{
    int c = threadIdx.x & 63;
    const float invN = 1.0f / (float)NN;
    float mu = g_stats[c] * invN;
    float var = g_stats[GC + c] * invN - mu * mu;
    float scale = rsqrtf(var + 1e-5f) * gamma[c];
    float shift = beta[c];
    for (int i = blockIdx.x * blockDim.x + threadIdx.x; i < NN * GC;
         i += gridDim.x * blockDim.x) {
        out[i] = (g_x[i] - mu) * scale + shift;
    }
}

// ---------------- launch ----------------
extern "C" void kernel_launch(void* const* d_in, const int* in_sizes, int n_in,
                              void* d_out, int out_size)
{
    const int*   atom   = (const int*)d_in[0];
    const float* pos    = (const float*)d_in[1];
    const int*   eidx   = (const int*)d_in[2];
    const float* emb    = (const float*)d_in[3];
    const float* pre_W  = (const float*)d_in[4];
    const float* pre_b  = (const float*)d_in[5];
    const float* Wf     = (const float*)d_in[6];
    const float* bf     = (const float*)d_in[7];
    const float* Ws     = (const float*)d_in[8];
    const float* bs     = (const float*)d_in[9];
    const float* gamma  = (const float*)d_in[10];
    const float* beta   = (const float*)d_in[11];
    const float* means  = (const float*)d_in[12];
    const float* betas  = (const float*)d_in[13];

    const int* src = eidx;
    const int* dst = eidx + NE;

    void *p_deg = nullptr, *p_agg = nullptr, *p_stats = nullptr;
    cudaGetSymbolAddress(&p_deg, g_deg);
    cudaGetSymbolAddress(&p_agg, g_agg);
    cudaGetSymbolAddress(&p_stats, g_stats);

    cudaFuncSetAttribute(proj_kernel, cudaFuncAttributeMaxDynamicSharedMemorySize, PROJ_SMEM);

    cudaMemsetAsync(p_deg, 0, NN * sizeof(float));
    edge_prep_kernel<<<2048, 256>>>(pos, src, dst, means, betas);
    inv_deg_kernel<<<(NN + 255) / 256, 256>>>();
    pre_table_kernel<<<NTYPES, GC>>>(emb, pre_W, pre_b);
    gather_x_kernel<<<2048, 256>>>(atom);

    for (int l = 0; l < NL; l++) {
        const float* Wf_l = Wf + (size_t)l * 160 * GC;
        const float* Ws_l = Ws + (size_t)l * 160 * GC;
        cudaMemsetAsync(p_agg, 0, (size_t)NN * GC * sizeof(float));
        cudaMemsetAsync(p_stats, 0, 2 * GC * sizeof(float));
        proj_kernel<<<444, 256, PROJ_SMEM>>>(Wf_l, Ws_l);
        msg_kernel<<<888, 256>>>(src, dst,
                                 Wf_l + 128 * GC, Ws_l + 128 * GC,
                                 bf + l * GC, bs + l * GC);
        update_stats_kernel<<<888, 256>>>();
        float* outp = (l == NL - 1) ? (float*)d_out : nullptr;
        if (!outp) {
            void* p_x = nullptr;
            cudaGetSymbolAddress(&p_x, g_x);
            outp = (float*)p_x;
        }
        bn_norm_kernel<<<888, 256>>>(gamma + l * GC, beta + l * GC, outp);
    }
}

// round 3
// speedup vs baseline: 1.1745x; 1.1745x over previous
#include <cuda_runtime.h>
#include <math.h>
#include <stdint.h>

#define NN 100000
#define NE 1200000
#define GC 64
#define RBF 32
#define NL 4
#define NF 92

// ---------------- scratch (static device globals) ----------------
__device__ float g_edge_attr[(size_t)NE * RBF];   // 153.6 MB
__device__ float g_proj[(size_t)NN * 4 * GC];     // 102.4 MB [n][Af|As|Bf|Bs]
__device__ float g_x[(size_t)NN * GC];            // 25.6 MB
__device__ int   g_deg[NN];
__device__ int   g_rowptr[NN];                    // exclusive CSR offsets
__device__ int   g_wofs[NN];                      // working copy for permute
__device__ int   g_esrc[NE];                      // src node, sorted by dst
__device__ int   g_eid[NE];                       // original edge id, sorted by dst
__device__ float g_stats[2 * GC];

// ---------------- launch 1: zero deg + x = relu(emb[atom] @ preW + b) ----------------
__global__ __launch_bounds__(256) void node_init_kernel(const int* __restrict__ atom,
                                                        const float* __restrict__ emb,
                                                        const float* __restrict__ preW,
                                                        const float* __restrict__ preb)
{
    for (int i = blockIdx.x * blockDim.x + threadIdx.x; i < NN; i += gridDim.x * blockDim.x)
        g_deg[i] = 0;

    int c = threadIdx.x & 63;
    int g = threadIdx.x >> 6;
    float bc = preb[c];
    for (int n = blockIdx.x * 4 + g; n < NN; n += gridDim.x * 4) {
        const float* er = &emb[atom[n] * NF];
        float acc = bc;
        #pragma unroll 4
        for (int f = 0; f < NF; f++)
            acc = fmaf(__ldg(&er[f]), preW[f * GC + c], acc);
        g_x[(size_t)n * GC + c] = fmaxf(acc, 0.0f);
    }
}

// ---------------- launch 2: edge prep: RBF*cutoff, deg count ----------------
__global__ void edge_prep_kernel(const float* __restrict__ pos,
                                 const int* __restrict__ src,
                                 const int* __restrict__ dst,
                                 const float* __restrict__ means,
                                 const float* __restrict__ betas)
{
    int lane = threadIdx.x & 31;
    int warp = (blockIdx.x * blockDim.x + threadIdx.x) >> 5;
    int nwarps = (gridDim.x * blockDim.x) >> 5;
    float mean = means[lane];
    float beta = betas[lane];
    for (int e = warp; e < NE; e += nwarps) {
        int s = src[e], d = dst[e];
        float dx = pos[s * 3 + 0] - pos[d * 3 + 0];
        float dy = pos[s * 3 + 1] - pos[d * 3 + 1];
        float dz = pos[s * 3 + 2] - pos[d * 3 + 2];
        float dist = sqrtf(dx * dx + dy * dy + dz * dz + 1e-12f);
        float cut = (dist < 5.0f) ? 0.5f * (__cosf(dist * 0.62831853071795f) + 1.0f) : 0.0f;
        float t = __expf(-dist) - mean;      // alpha = 1
        g_edge_attr[(size_t)e * RBF + lane] = cut * __expf(-beta * t * t);
        if (lane == 0) atomicAdd(&g_deg[d], 1);
    }
}

// ---------------- launch 3: single-block exclusive scan of deg -> rowptr, wofs ----------------
__global__ void scan_kernel()
{
    __shared__ int s[1024];
    int tid = threadIdx.x;
    int carry = 0;
    for (int base = 0; base < NN; base += 1024) {
        int idx = base + tid;
        int v = (idx < NN) ? g_deg[idx] : 0;
        s[tid] = v;
        __syncthreads();
        int x = v;
        for (int off = 1; off < 1024; off <<= 1) {
            int t = (tid >= off) ? s[tid - off] : 0;
            __syncthreads();
            x += t;
            s[tid] = x;
            __syncthreads();
        }
        if (idx < NN) {
            int excl = carry + x - v;
            g_rowptr[idx] = excl;
            g_wofs[idx] = excl;
        }
        carry += s[1023];
        __syncthreads();
    }
}

// ---------------- per-layer proj (+ optional one-time edge permute, + stats zero) ----------------
// [Af|As|Bf|Bs] = x @ {Wf[0:64], Ws[0:64], Wf[64:128], Ws[64:128]}
#define PROJ_SMEM ((4 * 64 * 64 + 16 * 64) * 4)
__global__ __launch_bounds__(256) void proj_kernel(const float* __restrict__ Wf_l,
                                                   const float* __restrict__ Ws_l,
                                                   const int* __restrict__ src,
                                                   const int* __restrict__ dst,
                                                   int do_permute)
{
    if (blockIdx.x == 0 && threadIdx.x < 2 * GC)
        g_stats[threadIdx.x] = 0.0f;

    if (do_permute) {
        for (int e = blockIdx.x * blockDim.x + threadIdx.x; e < NE;
             e += gridDim.x * blockDim.x) {
            int d = dst[e];
            int p = atomicAdd(&g_wofs[d], 1);
            g_esrc[p] = src[e];
            g_eid[p] = e;
        }
    }

    extern __shared__ float sm[];
    float* wsm = sm;                 // [4][64][64]
    float* xs  = sm + 4 * 64 * 64;   // [16][64]

    for (int i = threadIdx.x; i < 64 * 64; i += blockDim.x) {
        int k = i >> 6, c = i & 63;
        wsm[0 * 4096 + i] = Wf_l[k * GC + c];
        wsm[1 * 4096 + i] = Ws_l[k * GC + c];
        wsm[2 * 4096 + i] = Wf_l[(64 + k) * GC + c];
        wsm[3 * 4096 + i] = Ws_l[(64 + k) * GC + c];
    }

    int c = threadIdx.x & 63;
    int g = threadIdx.x >> 6;

    for (int nb = blockIdx.x * 16; nb < NN; nb += gridDim.x * 16) {
        __syncthreads();
        for (int i = threadIdx.x; i < 16 * 64; i += blockDim.x) {
            int nn = nb + (i >> 6);
            xs[i] = (nn < NN) ? g_x[(size_t)nn * GC + (i & 63)] : 0.0f;
        }
        __syncthreads();

        float acc[4][4] = {};
        #pragma unroll 16
        for (int k = 0; k < 64; k++) {
            float w0 = wsm[k * 64 + c];
            float w1 = wsm[4096 + k * 64 + c];
            float w2 = wsm[8192 + k * 64 + c];
            float w3 = wsm[12288 + k * 64 + c];
            #pragma unroll
            for (int j = 0; j < 4; j++) {
                float xv = xs[(g * 4 + j) * 64 + k];
                acc[j][0] = fmaf(xv, w0, acc[j][0]);
                acc[j][1] = fmaf(xv, w1, acc[j][1]);
                acc[j][2] = fmaf(xv, w2, acc[j][2]);
                acc[j][3] = fmaf(xv, w3, acc[j][3]);
            }
        }
        #pragma unroll
        for (int j = 0; j < 4; j++) {
            int n = nb + g * 4 + j;
            if (n < NN) {
                float* p = &g_proj[(size_t)n * 256];
                p[c]       = acc[j][0];
                p[64 + c]  = acc[j][1];
                p[128 + c] = acc[j][2];
                p[192 + c] = acc[j][3];
            }
        }
    }
}

// ---------------- fused CSR message + aggregate + residual + BN stats ----------------
__global__ __launch_bounds__(256, 2) void msg_csr_kernel(const float* __restrict__ Wfe,
                                                         const float* __restrict__ Wse,
                                                         const float* __restrict__ bfv,
                                                         const float* __restrict__ bsv)
{
    int c = threadIdx.x & 63;
    int g = threadIdx.x >> 6;

    float wf[RBF], ws[RBF];
    #pragma unroll
    for (int k = 0; k < RBF; k++) {
        wf[k] = Wfe[k * GC + c];
        ws[k] = Wse[k * GC + c];
    }
    float bfc = bfv[c], bsc = bsv[c];

    float lsum = 0.0f, lsq = 0.0f;

    for (int n = blockIdx.x * 4 + g; n < NN; n += gridDim.x * 4) {
        int start = g_rowptr[n];
        int deg = g_deg[n];
        const float* pd = &g_proj[(size_t)n * 256];
        float Af = pd[c];
        float As = pd[64 + c];
        float acc = 0.0f;

        #pragma unroll 2
        for (int i = 0; i < deg; i++) {
            int s = __ldg(&g_esrc[start + i]);
            int e = __ldg(&g_eid[start + i]);
            const float* ps = &g_proj[(size_t)s * 256];
            float f  = bfc + Af + ps[128 + c];
            float sv = bsc + As + ps[192 + c];
            const float4* ea4 = (const float4*)&g_edge_attr[(size_t)e * RBF];
            #pragma unroll
            for (int k4 = 0; k4 < RBF / 4; k4++) {
                float4 a = __ldg(&ea4[k4]);
                f  = fmaf(a.x, wf[4 * k4 + 0], f);
                f  = fmaf(a.y, wf[4 * k4 + 1], f);
                f  = fmaf(a.z, wf[4 * k4 + 2], f);
                f  = fmaf(a.w, wf[4 * k4 + 3], f);
                sv = fmaf(a.x, ws[4 * k4 + 0], sv);
                sv = fmaf(a.y, ws[4 * k4 + 1], sv);
                sv = fmaf(a.z, ws[4 * k4 + 2], sv);
                sv = fmaf(a.w, ws[4 * k4 + 3], sv);
            }
            float sig = __fdividef(1.0f, 1.0f + __expf(-f));
            float sp = (sv > 20.0f) ? sv : __logf(1.0f + __expf(sv));
            acc = fmaf(sig, sp, acc);
        }

        float inv = (deg > 0) ? __fdividef(1.0f, (float)deg) : 0.0f;
        float v = g_x[(size_t)n * GC + c] + acc * inv;
        g_x[(size_t)n * GC + c] = v;
        lsum += v;
        lsq = fmaf(v, v, lsq);
    }

    __shared__ float ssum[256], ssq[256];
    ssum[threadIdx.x] = lsum;
    ssq[threadIdx.x] = lsq;
    __syncthreads();
    if (g == 0) {
        float a = ssum[c] + ssum[64 + c] + ssum[128 + c] + ssum[192 + c];
        float b = ssq[c] + ssq[64 + c] + ssq[128 + c] + ssq[192 + c];
        atomicAdd(&g_stats[c], a);
        atomicAdd(&g_stats[GC + c], b);
    }
}

// ---------------- BN normalize ----------------
__global__ __launch_bounds__(256) void bn_norm_kernel(const float* __restrict__ gamma,
                                                      const float* __restrict__ beta,
                                                      float* __restrict__ out)
{
    int c = threadIdx.x & 63;
    const float invN = 1.0f / (float)NN;
    float mu = g_stats[c] * invN;
    float var = g_stats[GC + c] * invN - mu * mu;
    float scale = rsqrtf(var + 1e-5f) * gamma[c];
    float shift = beta[c];
    for (int i = blockIdx.x * blockDim.x + threadIdx.x; i < NN * GC;
         i += gridDim.x * blockDim.x) {
        out[i] = (g_x[i] - mu) * scale + shift;
    }
}

// ---------------- launch ----------------
extern "C" void kernel_launch(void* const* d_in, const int* in_sizes, int n_in,
                              void* d_out, int out_size)
{
    const int*   atom   = (const int*)d_in[0];
    const float* pos    = (const float*)d_in[1];
    const int*   eidx   = (const int*)d_in[2];
    const float* emb    = (const float*)d_in[3];
    const float* pre_W  = (const float*)d_in[4];
    const float* pre_b  = (const float*)d_in[5];
    const float* Wf     = (const float*)d_in[6];
    const float* bf     = (const float*)d_in[7];
    const float* Ws     = (const float*)d_in[8];
    const float* bs     = (const float*)d_in[9];
    const float* gamma  = (const float*)d_in[10];
    const float* beta   = (const float*)d_in[11];
    const float* means  = (const float*)d_in[12];
    const float* betas  = (const float*)d_in[13];

    const int* src = eidx;
    const int* dst = eidx + NE;

    cudaFuncSetAttribute(proj_kernel, cudaFuncAttributeMaxDynamicSharedMemorySize, PROJ_SMEM);

    void* p_x = nullptr;
    cudaGetSymbolAddress(&p_x, g_x);

    node_init_kernel<<<1024, 256>>>(atom, emb, pre_W, pre_b);        // L1
    edge_prep_kernel<<<2048, 256>>>(pos, src, dst, means, betas);    // L2
    scan_kernel<<<1, 1024>>>();                                      // L3

    for (int l = 0; l < NL; l++) {
        const float* Wf_l = Wf + (size_t)l * 160 * GC;
        const float* Ws_l = Ws + (size_t)l * 160 * GC;
        proj_kernel<<<444, 256, PROJ_SMEM>>>(Wf_l, Ws_l, src, dst, (l == 0) ? 1 : 0);
        msg_csr_kernel<<<1536, 256>>>(Wf_l + 128 * GC, Ws_l + 128 * GC,
                                      bf + l * GC, bs + l * GC);
        float* outp = (l == NL - 1) ? (float*)d_out : (float*)p_x;
        bn_norm_kernel<<<888, 256>>>(gamma + l * GC, beta + l * GC, outp);
    }
}

// round 4
// speedup vs baseline: 3.6493x; 3.1070x over previous
#include <cuda_runtime.h>
#include <math.h>
#include <stdint.h>

#define NN 100000
#define NE 1200000
#define GC 64
#define RBF 32
#define NL 4
#define NF 92
#define BINS 8192

// ---------------- scratch ----------------
__device__ float g_proj[(size_t)NN * 256];            // [n][(Af,As)x64 | (Bf,Bs)x64]
__device__ float g_x[(size_t)NN * GC];
__device__ int   g_deg[NN];                           // zero-init; re-zeroed by last bn
__device__ int   g_rowptr[NN];
__device__ int   g_wofs[NN];
__device__ float g_t[NE];                             // table coordinate per edge
__device__ int2  g_einfo[NE];                         // CSR-sorted: (src, t bits)
__device__ float g_table4[(size_t)NL * (BINS + 2) * 128];  // [l][bin][(Ff,Fs)x64]
__device__ float g_stats[2 * GC];

#define GE 2048
#define GT 129
#define GN 1024

// ---------------- launch 1: edge prep + RBF tables + node init (fused) ----------------
__global__ __launch_bounds__(256) void prep_kernel(const float* __restrict__ pos,
                                                   const int* __restrict__ src,
                                                   const int* __restrict__ dst,
                                                   const float* __restrict__ means,
                                                   const float* __restrict__ betas,
                                                   const int* __restrict__ atom,
                                                   const float* __restrict__ emb,
                                                   const float* __restrict__ preW,
                                                   const float* __restrict__ preb,
                                                   const float* __restrict__ Wf,
                                                   const float* __restrict__ Ws)
{
    int bid = blockIdx.x;
    int tid = threadIdx.x;

    if (bid < GE) {
        // ---- edges: distance -> table coordinate; degree count ----
        for (int e = bid * 256 + tid; e < NE; e += GE * 256) {
            int s = src[e], d = dst[e];
            float dx = pos[s * 3 + 0] - pos[d * 3 + 0];
            float dy = pos[s * 3 + 1] - pos[d * 3 + 1];
            float dz = pos[s * 3 + 2] - pos[d * 3 + 2];
            float dist = sqrtf(dx * dx + dy * dy + dz * dz + 1e-12f);
            g_t[e] = fminf(dist, 5.0f) * ((float)BINS / 5.0f);
            atomicAdd(&g_deg[d], 1);
        }
    } else if (bid < GE + GT) {
        // ---- RBF projection tables: F_{f,s}(d) for all 4 layers ----
        int tb = bid - GE;                 // this block: bins [tb*64, tb*64+64)
        __shared__ float ea[64][RBF];
        __shared__ float sw[2 * RBF * GC];
        for (int i = tid; i < 64 * RBF; i += 256) {
            int bb = i >> 5, k = i & 31;
            int bin = tb * 64 + bb;
            float dd = (float)bin * (5.0f / (float)BINS);
            float cut = (dd < 5.0f) ? 0.5f * (cosf(dd * 0.62831853071795f) + 1.0f) : 0.0f;
            float u = expf(-dd) - means[k];
            ea[bb][k] = cut * expf(-betas[k] * u * u);
        }
        __syncthreads();
        for (int l = 0; l < NL; l++) {
            const float* WfE = Wf + (size_t)l * 160 * GC + 128 * GC;
            const float* WsE = Ws + (size_t)l * 160 * GC + 128 * GC;
            for (int i = tid; i < RBF * GC; i += 256) {
                sw[i] = WfE[i];
                sw[RBF * GC + i] = WsE[i];
            }
            __syncthreads();
            for (int it = tid; it < 64 * 128; it += 256) {
                int bb = it >> 7, j = it & 127;
                int col = j >> 1;
                const float* w = (j & 1) ? (sw + RBF * GC) : sw;
                float a = 0.0f;
                #pragma unroll
                for (int k = 0; k < RBF; k++)
                    a = fmaf(ea[bb][k], w[k * GC + col], a);
                int bin = tb * 64 + bb;
                if (bin < BINS + 2)
                    g_table4[((size_t)l * (BINS + 2) + bin) * 128 + j] = a;
            }
            __syncthreads();
        }
    } else {
        // ---- node init: x = relu(emb[atom] @ preW + b) ----
        int nb = bid - GE - GT;
        int c = tid & 63, g = tid >> 6;
        float bc = preb[c];
        for (int n = nb * 4 + g; n < NN; n += GN * 4) {
            const float* er = &emb[atom[n] * NF];
            float acc = bc;
            #pragma unroll 4
            for (int f = 0; f < NF; f++)
                acc = fmaf(__ldg(&er[f]), preW[f * GC + c], acc);
            g_x[(size_t)n * GC + c] = fmaxf(acc, 0.0f);
        }
    }
}

// ---------------- launch 2: exclusive scan of deg -> rowptr, wofs ----------------
__global__ void scan_kernel()
{
    __shared__ int s[1024];
    int tid = threadIdx.x;
    int carry = 0;
    for (int base = 0; base < NN; base += 1024) {
        int idx = base + tid;
        int v = (idx < NN) ? g_deg[idx] : 0;
        s[tid] = v;
        __syncthreads();
        int x = v;
        for (int off = 1; off < 1024; off <<= 1) {
            int t = (tid >= off) ? s[tid - off] : 0;
            __syncthreads();
            x += t;
            s[tid] = x;
            __syncthreads();
        }
        if (idx < NN) {
            int excl = carry + x - v;
            g_rowptr[idx] = excl;
            g_wofs[idx] = excl;
        }
        carry += s[1023];
        __syncthreads();
    }
}

// ---------------- per-layer proj (+ one-time edge permute, stats zero) ----------------
#define PROJ_SMEM ((4 * 64 * 64 + 32 * 64) * 4)
__global__ __launch_bounds__(256) void proj_kernel(const float* __restrict__ Wf_l,
                                                   const float* __restrict__ Ws_l,
                                                   const int* __restrict__ src,
                                                   const int* __restrict__ dst,
                                                   int do_permute)
{
    if (blockIdx.x == 0 && threadIdx.x < 2 * GC)
        g_stats[threadIdx.x] = 0.0f;

    if (do_permute) {
        for (int e = blockIdx.x * blockDim.x + threadIdx.x; e < NE;
             e += gridDim.x * blockDim.x) {
            int d = dst[e];
            int p = atomicAdd(&g_wofs[d], 1);
            g_einfo[p] = make_int2(src[e], __float_as_int(g_t[e]));
        }
    }

    extern __shared__ float sm[];
    float* wsm = sm;                 // [4][64][64]
    float* xs  = sm + 4 * 64 * 64;   // [32][64]

    for (int i = threadIdx.x; i < 64 * 64; i += blockDim.x) {
        int k = i >> 6, c = i & 63;
        wsm[0 * 4096 + i] = Wf_l[k * GC + c];            // Af
        wsm[1 * 4096 + i] = Ws_l[k * GC + c];            // As
        wsm[2 * 4096 + i] = Wf_l[(64 + k) * GC + c];     // Bf
        wsm[3 * 4096 + i] = Ws_l[(64 + k) * GC + c];     // Bs
    }

    int c = threadIdx.x & 63;
    int g = threadIdx.x >> 6;   // 4 groups x 8 nodes = 32-node tile

    for (int nb = blockIdx.x * 32; nb < NN; nb += gridDim.x * 32) {
        __syncthreads();
        for (int i = threadIdx.x; i < 32 * 64; i += blockDim.x) {
            int nn = nb + (i >> 6);
            xs[i] = (nn < NN) ? g_x[(size_t)nn * GC + (i & 63)] : 0.0f;
        }
        __syncthreads();

        float acc[8][4] = {};
        #pragma unroll 8
        for (int k = 0; k < 64; k++) {
            float w0 = wsm[k * 64 + c];
            float w1 = wsm[4096 + k * 64 + c];
            float w2 = wsm[8192 + k * 64 + c];
            float w3 = wsm[12288 + k * 64 + c];
            #pragma unroll
            for (int j = 0; j < 8; j++) {
                float xv = xs[(g * 8 + j) * 64 + k];
                acc[j][0] = fmaf(xv, w0, acc[j][0]);
                acc[j][1] = fmaf(xv, w1, acc[j][1]);
                acc[j][2] = fmaf(xv, w2, acc[j][2]);
                acc[j][3] = fmaf(xv, w3, acc[j][3]);
            }
        }
        #pragma unroll
        for (int j = 0; j < 8; j++) {
            int n = nb + g * 8 + j;
            if (n < NN) {
                float* p = &g_proj[(size_t)n * 256];
                *(float2*)&p[2 * c]       = make_float2(acc[j][0], acc[j][1]);  // Af,As
                *(float2*)&p[128 + 2 * c] = make_float2(acc[j][2], acc[j][3]);  // Bf,Bs
            }
        }
    }
}

// ---------------- fused CSR message + aggregate + residual + BN stats ----------------
__global__ __launch_bounds__(256) void msg_kernel(const float* __restrict__ tabL,
                                                  const float* __restrict__ bfv,
                                                  const float* __restrict__ bsv)
{
    int c = threadIdx.x & 63;
    int g = threadIdx.x >> 6;
    float bfc = bfv[c], bsc = bsv[c];

    float lsum = 0.0f, lsq = 0.0f;

    for (int n = blockIdx.x * 4 + g; n < NN; n += gridDim.x * 4) {
        int start = g_rowptr[n];
        int deg = g_deg[n];
        float2 A = *(const float2*)&g_proj[(size_t)n * 256 + 2 * c];
        float basef = bfc + A.x;
        float bases = bsc + A.y;
        float acc = 0.0f;

        #pragma unroll 2
        for (int i = 0; i < deg; i++) {
            int2 se = __ldg(&g_einfo[start + i]);
            float t = __int_as_float(se.y);
            int b = (int)t;
            float fr = t - (float)b;
            float2 B = *(const float2*)&g_proj[(size_t)se.x * 256 + 128 + 2 * c];
            const float* r0 = tabL + (size_t)b * 128 + 2 * c;
            float2 T0 = *(const float2*)r0;
            float2 T1 = *(const float2*)(r0 + 128);
            float f  = basef + B.x + T0.x + fr * (T1.x - T0.x);
            float sv = bases + B.y + T0.y + fr * (T1.y - T0.y);
            float sig = __fdividef(1.0f, 1.0f + __expf(-f));
            float sp = (sv > 20.0f) ? sv : __logf(1.0f + __expf(sv));
            acc = fmaf(sig, sp, acc);
        }

        float inv = (deg > 0) ? __fdividef(1.0f, (float)deg) : 0.0f;
        float v = g_x[(size_t)n * GC + c] + acc * inv;
        g_x[(size_t)n * GC + c] = v;
        lsum += v;
        lsq = fmaf(v, v, lsq);
    }

    __shared__ float ssum[256], ssq[256];
    ssum[threadIdx.x] = lsum;
    ssq[threadIdx.x] = lsq;
    __syncthreads();
    if (g == 0) {
        float a = ssum[c] + ssum[64 + c] + ssum[128 + c] + ssum[192 + c];
        float b = ssq[c] + ssq[64 + c] + ssq[128 + c] + ssq[192 + c];
        atomicAdd(&g_stats[c], a);
        atomicAdd(&g_stats[GC + c], b);
    }
}

// ---------------- BN normalize (+ deg re-zero on last layer for graph replay) ----------------
__global__ __launch_bounds__(256) void bn_norm_kernel(const float* __restrict__ gamma,
                                                      const float* __restrict__ beta,
                                                      float* __restrict__ out,
                                                      int zero_deg)
{
    int c = threadIdx.x & 63;
    const float invN = 1.0f / (float)NN;
    float mu = g_stats[c] * invN;
    float var = g_stats[GC + c] * invN - mu * mu;
    float scale = rsqrtf(var + 1e-5f) * gamma[c];
    float shift = beta[c];
    for (int i = blockIdx.x * blockDim.x + threadIdx.x; i < NN * GC;
         i += gridDim.x * blockDim.x) {
        out[i] = (g_x[i] - mu) * scale + shift;
    }
    if (zero_deg) {
        for (int i = blockIdx.x * blockDim.x + threadIdx.x; i < NN;
             i += gridDim.x * blockDim.x)
            g_deg[i] = 0;
    }
}

// ---------------- launch ----------------
extern "C" void kernel_launch(void* const* d_in, const int* in_sizes, int n_in,
                              void* d_out, int out_size)
{
    const int*   atom   = (const int*)d_in[0];
    const float* pos    = (const float*)d_in[1];
    const int*   eidx   = (const int*)d_in[2];
    const float* emb    = (const float*)d_in[3];
    const float* pre_W  = (const float*)d_in[4];
    const float* pre_b  = (const float*)d_in[5];
    const float* Wf     = (const float*)d_in[6];
    const float* bf     = (const float*)d_in[7];
    const float* Ws     = (const float*)d_in[8];
    const float* bs     = (const float*)d_in[9];
    const float* gamma  = (const float*)d_in[10];
    const float* beta   = (const float*)d_in[11];
    const float* means  = (const float*)d_in[12];
    const float* betas  = (const float*)d_in[13];

    const int* src = eidx;
    const int* dst = eidx + NE;

    cudaFuncSetAttribute(proj_kernel, cudaFuncAttributeMaxDynamicSharedMemorySize, PROJ_SMEM);

    void* p_x = nullptr;
    cudaGetSymbolAddress(&p_x, g_x);
    void* p_tab = nullptr;
    cudaGetSymbolAddress(&p_tab, g_table4);

    prep_kernel<<<GE + GT + GN, 256>>>(pos, src, dst, means, betas,
                                       atom, emb, pre_W, pre_b, Wf, Ws);   // L1
    scan_kernel<<<1, 1024>>>();                                            // L2

    for (int l = 0; l < NL; l++) {
        const float* Wf_l = Wf + (size_t)l * 160 * GC;
        const float* Ws_l = Ws + (size_t)l * 160 * GC;
        const float* tabL = (const float*)p_tab + (size_t)l * (BINS + 2) * 128;
        proj_kernel<<<444, 256, PROJ_SMEM>>>(Wf_l, Ws_l, src, dst, (l == 0) ? 1 : 0);
        msg_kernel<<<2048, 256>>>(tabL, bf + l * GC, bs + l * GC);         // L4 on l==0
        float* outp = (l == NL - 1) ? (float*)d_out : (float*)p_x;
        bn_norm_kernel<<<888, 256>>>(gamma + l * GC, beta + l * GC, outp,
                                     (l == NL - 1) ? 1 : 0);
    }
}

// round 5
// speedup vs baseline: 3.9004x; 1.0688x over previous
#include <cuda_runtime.h>
#include <cuda_fp16.h>
#include <math.h>
#include <stdint.h>

#define NN 100000
#define NE 1200000
#define GC 64
#define RBF 32
#define NL 4
#define NF 92
#define BINS 8192

// ---------------- scratch ----------------
__device__ float2 g_projA[(size_t)NN * GC];             // (Af,As) fp32, 51.2 MB
__device__ __half2 g_projB[(size_t)NN * GC];            // (Bf,Bs) fp16, 25.6 MB (L2-resident)
__device__ float  g_x[(size_t)NN * GC];                 // raw (pre-BN) features
__device__ int    g_deg[NN];                            // zero-init; re-zeroed by final bn
__device__ int    g_rowptr[NN];
__device__ int    g_wofs[NN];
__device__ float  g_t[NE];
__device__ int2   g_einfo[NE];                          // (src*64, t bits), CSR-sorted by dst
__device__ uint2  g_tab[(size_t)NL * (BINS + 2) * GC];  // [(F(b),F(b+1))] packed halves
__device__ float  g_stats[2 * 128];                     // double-buffered [parity][sum|sq]

#define GE 2048
#define GT 129
#define GN 1024

// ---------------- launch 1: edge prep + RBF pair-tables + node init (fused) ----------------
__global__ __launch_bounds__(256) void prep_kernel(const float* __restrict__ pos,
                                                   const int* __restrict__ src,
                                                   const int* __restrict__ dst,
                                                   const float* __restrict__ means,
                                                   const float* __restrict__ betas,
                                                   const int* __restrict__ atom,
                                                   const float* __restrict__ emb,
                                                   const float* __restrict__ preW,
                                                   const float* __restrict__ preb,
                                                   const float* __restrict__ Wf,
                                                   const float* __restrict__ Ws)
{
    int bid = blockIdx.x;
    int tid = threadIdx.x;

    if (bid < GE) {
        for (int e = bid * 256 + tid; e < NE; e += GE * 256) {
            int s = src[e], d = dst[e];
            float dx = pos[s * 3 + 0] - pos[d * 3 + 0];
            float dy = pos[s * 3 + 1] - pos[d * 3 + 1];
            float dz = pos[s * 3 + 2] - pos[d * 3 + 2];
            float dist = sqrtf(dx * dx + dy * dy + dz * dz + 1e-12f);
            g_t[e] = fminf(dist, 5.0f) * ((float)BINS / 5.0f);
            atomicAdd(&g_deg[d], 1);
        }
    } else if (bid < GE + GT) {
        // table block: bins [tb*64, tb*64+64); computes 65 local bins for pairing
        int tb = bid - GE;
        __shared__ float ea[65][RBF];
        __shared__ float sw[2 * RBF * GC];
        __shared__ __half2 sF[65][GC];
        for (int i = tid; i < 65 * RBF; i += 256) {
            int bb = i >> 5, k = i & 31;
            float dd = (float)(tb * 64 + bb) * (5.0f / (float)BINS);
            float cut = (dd < 5.0f) ? 0.5f * (cosf(dd * 0.62831853071795f) + 1.0f) : 0.0f;
            float u = expf(-dd) - means[k];
            ea[bb][k] = cut * expf(-betas[k] * u * u);
        }
        __syncthreads();
        for (int l = 0; l < NL; l++) {
            const float* WfE = Wf + (size_t)l * 160 * GC + 128 * GC;
            const float* WsE = Ws + (size_t)l * 160 * GC + 128 * GC;
            for (int i = tid; i < RBF * GC; i += 256) {
                sw[i] = WfE[i];
                sw[RBF * GC + i] = WsE[i];
            }
            __syncthreads();
            for (int it = tid; it < 65 * GC; it += 256) {
                int bb = it >> 6, c = it & 63;
                float af = 0.0f, as = 0.0f;
                #pragma unroll
                for (int k = 0; k < RBF; k++) {
                    float e_ = ea[bb][k];
                    af = fmaf(e_, sw[k * GC + c], af);
                    as = fmaf(e_, sw[RBF * GC + k * GC + c], as);
                }
                sF[bb][c] = __floats2half2_rn(af, as);
            }
            __syncthreads();
            for (int it = tid; it < 64 * GC; it += 256) {
                int bb = it >> 6, c = it & 63;
                int bin = tb * 64 + bb;
                if (bin < BINS + 2) {
                    uint2 v;
                    v.x = *reinterpret_cast<uint32_t*>(&sF[bb][c]);
                    v.y = *reinterpret_cast<uint32_t*>(&sF[bb + 1][c]);
                    g_tab[((size_t)l * (BINS + 2) + bin) * GC + c] = v;
                }
            }
            __syncthreads();
        }
    } else {
        int nb = bid - GE - GT;
        int c = tid & 63, g = tid >> 6;
        float bc = preb[c];
        for (int n = nb * 4 + g; n < NN; n += GN * 4) {
            const float* er = &emb[atom[n] * NF];
            float acc = bc;
            #pragma unroll 4
            for (int f = 0; f < NF; f++)
                acc = fmaf(__ldg(&er[f]), preW[f * GC + c], acc);
            g_x[(size_t)n * GC + c] = fmaxf(acc, 0.0f);
        }
    }
}

// ---------------- launch 2: shfl-based exclusive scan ----------------
__global__ void scan_kernel()
{
    __shared__ int wsum[32];
    __shared__ int wexcl[32];
    __shared__ int stotal;
    int tid = threadIdx.x, lane = tid & 31, wid = tid >> 5;
    int carry = 0;
    for (int base = 0; base < NN; base += 4096) {
        int i0 = base + tid * 4;
        int a0 = (i0 + 0 < NN) ? g_deg[i0 + 0] : 0;
        int a1 = (i0 + 1 < NN) ? g_deg[i0 + 1] : 0;
        int a2 = (i0 + 2 < NN) ? g_deg[i0 + 2] : 0;
        int a3 = (i0 + 3 < NN) ? g_deg[i0 + 3] : 0;
        int s0 = a0, s1 = s0 + a1, s2 = s1 + a2, s3 = s2 + a3;
        int inc = s3;
        #pragma unroll
        for (int off = 1; off < 32; off <<= 1) {
            int t = __shfl_up_sync(0xffffffffu, inc, off);
            if (lane >= off) inc += t;
        }
        if (lane == 31) wsum[wid] = inc;
        __syncthreads();
        if (wid == 0) {
            int w = wsum[lane];
            int wi = w;
            #pragma unroll
            for (int off = 1; off < 32; off <<= 1) {
                int t = __shfl_up_sync(0xffffffffu, wi, off);
                if (lane >= off) wi += t;
            }
            wexcl[lane] = wi - w;
            if (lane == 31) stotal = wi;
        }
        __syncthreads();
        int excl = carry + wexcl[wid] + (inc - s3);
        if (i0 + 0 < NN) { g_rowptr[i0 + 0] = excl;      g_wofs[i0 + 0] = excl; }
        if (i0 + 1 < NN) { g_rowptr[i0 + 1] = excl + s0; g_wofs[i0 + 1] = excl + s0; }
        if (i0 + 2 < NN) { g_rowptr[i0 + 2] = excl + s1; g_wofs[i0 + 2] = excl + s1; }
        if (i0 + 3 < NN) { g_rowptr[i0 + 3] = excl + s2; g_wofs[i0 + 3] = excl + s2; }
        carry += stotal;
        __syncthreads();
    }
}

// ---------------- per-layer proj (+ one-time permute, stats-zero, BN-on-read) ----------------
#define PROJ_SMEM ((4 * 64 * 64 + 32 * 64) * 4)
__global__ __launch_bounds__(256) void proj_kernel(const float* __restrict__ Wf_l,
                                                   const float* __restrict__ Ws_l,
                                                   const int* __restrict__ src,
                                                   const int* __restrict__ dst,
                                                   int do_permute,
                                                   const float* __restrict__ stats_prev,
                                                   const float* __restrict__ gamma_prev,
                                                   const float* __restrict__ beta_prev,
                                                   int apply_bn, int zero_parity)
{
    if (blockIdx.x == 0 && threadIdx.x < 128)
        g_stats[zero_parity * 128 + threadIdx.x] = 0.0f;

    if (do_permute) {
        for (int e = blockIdx.x * blockDim.x + threadIdx.x; e < NE;
             e += gridDim.x * blockDim.x) {
            int d = dst[e];
            int p = atomicAdd(&g_wofs[d], 1);
            g_einfo[p] = make_int2(src[e] * GC, __float_as_int(g_t[e]));
        }
    }

    extern __shared__ float sm[];
    float* wsm = sm;                 // [4][64][64]
    float* xs  = sm + 4 * 64 * 64;   // [32][64]
    __shared__ float ksc[64], ksh[64];

    if (threadIdx.x < 64) {
        float s = 1.0f, t = 0.0f;
        if (apply_bn) {
            const float invN = 1.0f / (float)NN;
            float mu = stats_prev[threadIdx.x] * invN;
            float var = stats_prev[64 + threadIdx.x] * invN - mu * mu;
            s = rsqrtf(var + 1e-5f) * gamma_prev[threadIdx.x];
            t = beta_prev[threadIdx.x] - mu * s;
        }
        ksc[threadIdx.x] = s;
        ksh[threadIdx.x] = t;
    }

    for (int i = threadIdx.x; i < 64 * 64; i += blockDim.x) {
        int k = i >> 6, c = i & 63;
        wsm[0 * 4096 + i] = Wf_l[k * GC + c];
        wsm[1 * 4096 + i] = Ws_l[k * GC + c];
        wsm[2 * 4096 + i] = Wf_l[(64 + k) * GC + c];
        wsm[3 * 4096 + i] = Ws_l[(64 + k) * GC + c];
    }

    int c = threadIdx.x & 63;
    int g = threadIdx.x >> 6;

    for (int nb = blockIdx.x * 32; nb < NN; nb += gridDim.x * 32) {
        __syncthreads();
        for (int i = threadIdx.x; i < 32 * 64; i += blockDim.x) {
            int nn = nb + (i >> 6);
            int cc = i & 63;
            xs[i] = (nn < NN)
                  ? fmaf(g_x[(size_t)nn * GC + cc], ksc[cc], ksh[cc]) : 0.0f;
        }
        __syncthreads();

        float acc[8][4] = {};
        #pragma unroll 8
        for (int k = 0; k < 64; k++) {
            float w0 = wsm[k * 64 + c];
            float w1 = wsm[4096 + k * 64 + c];
            float w2 = wsm[8192 + k * 64 + c];
            float w3 = wsm[12288 + k * 64 + c];
            #pragma unroll
            for (int j = 0; j < 8; j++) {
                float xv = xs[(g * 8 + j) * 64 + k];
                acc[j][0] = fmaf(xv, w0, acc[j][0]);
                acc[j][1] = fmaf(xv, w1, acc[j][1]);
                acc[j][2] = fmaf(xv, w2, acc[j][2]);
                acc[j][3] = fmaf(xv, w3, acc[j][3]);
            }
        }
        #pragma unroll
        for (int j = 0; j < 8; j++) {
            int n = nb + g * 8 + j;
            if (n < NN) {
                g_projA[(size_t)n * GC + c] = make_float2(acc[j][0], acc[j][1]);
                g_projB[(size_t)n * GC + c] = __floats2half2_rn(acc[j][2], acc[j][3]);
            }
        }
    }
}

// ---------------- fused CSR message + aggregate + residual + BN stats ----------------
__global__ __launch_bounds__(256) void msg_kernel(const uint2* __restrict__ tabL,
                                                  const float* __restrict__ bfv,
                                                  const float* __restrict__ bsv,
                                                  const float* __restrict__ stats_prev,
                                                  const float* __restrict__ gamma_prev,
                                                  const float* __restrict__ beta_prev,
                                                  int apply_bn,
                                                  float* __restrict__ stats_out)
{
    int c = threadIdx.x & 63;
    int g = threadIdx.x >> 6;
    float bfc = bfv[c], bsc = bsv[c];

    float kscale = 1.0f, kshift = 0.0f;
    if (apply_bn) {
        const float invN = 1.0f / (float)NN;
        float mu = stats_prev[c] * invN;
        float var = stats_prev[64 + c] * invN - mu * mu;
        kscale = rsqrtf(var + 1e-5f) * gamma_prev[c];
        kshift = beta_prev[c] - mu * kscale;
    }

    float lsum = 0.0f, lsq = 0.0f;

    for (int n = blockIdx.x * 4 + g; n < NN; n += gridDim.x * 4) {
        int start = g_rowptr[n];
        int deg = g_deg[n];
        float2 A = __ldg(&g_projA[(size_t)n * GC + c]);
        float basef = bfc + A.x;
        float bases = bsc + A.y;
        float acc = 0.0f;

        #pragma unroll 2
        for (int i = 0; i < deg; i++) {
            int2 se = __ldg(&g_einfo[start + i]);
            float t = __int_as_float(se.y);
            int b = (int)t;
            float fr = t - (float)b;
            float2 B = __half22float2(__ldg(&g_projB[se.x + c]));
            uint2 r = __ldg(&tabL[b * GC + c]);
            float2 T0 = __half22float2(*reinterpret_cast<__half2*>(&r.x));
            float2 T1 = __half22float2(*reinterpret_cast<__half2*>(&r.y));
            float f  = basef + B.x + fmaf(fr, T1.x - T0.x, T0.x);
            float sv = bases + B.y + fmaf(fr, T1.y - T0.y, T0.y);
            float sig = __fdividef(1.0f, 1.0f + __expf(-f));
            float sp = (sv > 20.0f) ? sv : __logf(1.0f + __expf(sv));
            acc = fmaf(sig, sp, acc);
        }

        float inv = (deg > 0) ? __fdividef(1.0f, (float)deg) : 0.0f;
        size_t xi = (size_t)n * GC + c;
        float v = fmaf(g_x[xi], kscale, kshift) + acc * inv;
        g_x[xi] = v;
        lsum += v;
        lsq = fmaf(v, v, lsq);
    }

    __shared__ float ssum[256], ssq[256];
    ssum[threadIdx.x] = lsum;
    ssq[threadIdx.x] = lsq;
    __syncthreads();
    if (g == 0) {
        float a = ssum[c] + ssum[64 + c] + ssum[128 + c] + ssum[192 + c];
        float b = ssq[c] + ssq[64 + c] + ssq[128 + c] + ssq[192 + c];
        atomicAdd(&stats_out[c], a);
        atomicAdd(&stats_out[GC + c], b);
    }
}

// ---------------- final BN normalize (+ deg re-zero for graph replay) ----------------
__global__ __launch_bounds__(256) void bn_norm_kernel(const float* __restrict__ stats,
                                                      const float* __restrict__ gamma,
                                                      const float* __restrict__ beta,
                                                      float* __restrict__ out)
{
    int c = threadIdx.x & 63;
    const float invN = 1.0f / (float)NN;
    float mu = stats[c] * invN;
    float var = stats[GC + c] * invN - mu * mu;
    float scale = rsqrtf(var + 1e-5f) * gamma[c];
    float shift = beta[c] - mu * scale;
    for (int i = blockIdx.x * blockDim.x + threadIdx.x; i < NN * GC;
         i += gridDim.x * blockDim.x) {
        out[i] = fmaf(g_x[i], scale, shift);
    }
    for (int i = blockIdx.x * blockDim.x + threadIdx.x; i < NN;
         i += gridDim.x * blockDim.x)
        g_deg[i] = 0;
}

// ---------------- launch ----------------
extern "C" void kernel_launch(void* const* d_in, const int* in_sizes, int n_in,
                              void* d_out, int out_size)
{
    const int*   atom   = (const int*)d_in[0];
    const float* pos    = (const float*)d_in[1];
    const int*   eidx   = (const int*)d_in[2];
    const float* emb    = (const float*)d_in[3];
    const float* pre_W  = (const float*)d_in[4];
    const float* pre_b  = (const float*)d_in[5];
    const float* Wf     = (const float*)d_in[6];
    const float* bf     = (const float*)d_in[7];
    const float* Ws     = (const float*)d_in[8];
    const float* bs     = (const float*)d_in[9];
    const float* gamma  = (const float*)d_in[10];
    const float* beta   = (const float*)d_in[11];
    const float* means  = (const float*)d_in[12];
    const float* betas  = (const float*)d_in[13];

    const int* src = eidx;
    const int* dst = eidx + NE;

    cudaFuncSetAttribute(proj_kernel, cudaFuncAttributeMaxDynamicSharedMemorySize, PROJ_SMEM);

    void* p_tab = nullptr;
    cudaGetSymbolAddress(&p_tab, g_tab);
    void* p_stats = nullptr;
    cudaGetSymbolAddress(&p_stats, g_stats);
    float* stats = (float*)p_stats;

    prep_kernel<<<GE + GT + GN, 256>>>(pos, src, dst, means, betas,
                                       atom, emb, pre_W, pre_b, Wf, Ws);   // L1
    scan_kernel<<<1, 1024>>>();                                            // L2

    for (int l = 0; l < NL; l++) {
        const float* Wf_l = Wf + (size_t)l * 160 * GC;
        const float* Ws_l = Ws + (size_t)l * 160 * GC;
        const uint2* tabL = (const uint2*)p_tab + (size_t)l * (BINS + 2) * GC;
        const float* sprev = stats + ((l - 1) & 1) * 128;
        float* sout = stats + (l & 1) * 128;
        int apply = (l > 0) ? 1 : 0;
        const float* gprev = gamma + (l - 1) * GC;
        const float* bprev = beta + (l - 1) * GC;
        proj_kernel<<<444, 256, PROJ_SMEM>>>(Wf_l, Ws_l, src, dst, (l == 0) ? 1 : 0,
                                             sprev, gprev, bprev, apply, l & 1);
        msg_kernel<<<2048, 256>>>(tabL, bf + l * GC, bs + l * GC,
                                  sprev, gprev, bprev, apply, sout);       // slot 4 on l==0
    }
    bn_norm_kernel<<<888, 256>>>(stats + ((NL - 1) & 1) * 128,
                                 gamma + (NL - 1) * GC, beta + (NL - 1) * GC,
                                 (float*)d_out);
}

// round 6
// speedup vs baseline: 4.0321x; 1.0338x over previous
#include <cuda_runtime.h>
#include <cuda_fp16.h>
#include <math.h>
#include <stdint.h>

#define NN 100000
#define NE 1200000
#define GC 64
#define RBF 32
#define NL 4
#define NF 92
#define BINS 8192
#define LOG2E 1.44269504088896f
#define LN2 0.69314718055995f

// ---------------- scratch ----------------
__device__ float2  g_projA[(size_t)NN * GC];            // (Af',As') fp32 (log2e-scaled)
__device__ __half2 g_projB[(size_t)NN * GC];            // (Bf',Bs') fp16
__device__ float   g_x[(size_t)NN * GC];                // raw (pre-BN) features
__device__ int     g_deg[NN];                           // zero-init; re-zeroed by final bn
__device__ int     g_rowptr[NN];
__device__ int     g_wofs[NN];
__device__ float   g_invdeg[NN];                        // ln2/deg
__device__ float   g_t[NE];
__device__ int4    g_meta[NE];                          // (src*256, bin*512, half2(fr,fr), 0)
__device__ uint2   g_tab[(size_t)NL * (BINS + 2) * GC]; // {half2(T0f,T0s), half2(dTf,dTs)} log2e-scaled
__device__ float   g_stats[2 * 128];

#define GE 2048
#define GT 129
#define GN 1024

__device__ __forceinline__ float fast_ex2(float x){ float r; asm("ex2.approx.f32 %0,%1;":"=f"(r):"f"(x)); return r; }
__device__ __forceinline__ float fast_lg2(float x){ float r; asm("lg2.approx.f32 %0,%1;":"=f"(r):"f"(x)); return r; }
__device__ __forceinline__ float fast_rcp(float x){ float r; asm("rcp.approx.f32 %0,%1;":"=f"(r):"f"(x)); return r; }

// ---------------- launch 1: edge prep + RBF pair-tables + node init (fused) ----------------
__global__ __launch_bounds__(256) void prep_kernel(const float* __restrict__ pos,
                                                   const int* __restrict__ src,
                                                   const int* __restrict__ dst,
                                                   const float* __restrict__ means,
                                                   const float* __restrict__ betas,
                                                   const int* __restrict__ atom,
                                                   const float* __restrict__ emb,
                                                   const float* __restrict__ preW,
                                                   const float* __restrict__ preb,
                                                   const float* __restrict__ Wf,
                                                   const float* __restrict__ Ws)
{
    int bid = blockIdx.x;
    int tid = threadIdx.x;

    if (bid < GE) {
        for (int e = bid * 256 + tid; e < NE; e += GE * 256) {
            int s = src[e], d = dst[e];
            float dx = pos[s * 3 + 0] - pos[d * 3 + 0];
            float dy = pos[s * 3 + 1] - pos[d * 3 + 1];
            float dz = pos[s * 3 + 2] - pos[d * 3 + 2];
            float dist = sqrtf(dx * dx + dy * dy + dz * dz + 1e-12f);
            g_t[e] = fminf(dist, 5.0f) * ((float)BINS / 5.0f);
            atomicAdd(&g_deg[d], 1);
        }
    } else if (bid < GE + GT) {
        int tb = bid - GE;   // bins [tb*64, tb*64+64); compute 65 for pairing
        __shared__ float ea[65][RBF];
        __shared__ float sw[2 * RBF * GC];
        __shared__ __half2 sF[65][GC];
        for (int i = tid; i < 65 * RBF; i += 256) {
            int bb = i >> 5, k = i & 31;
            float dd = (float)(tb * 64 + bb) * (5.0f / (float)BINS);
            float cut = (dd < 5.0f) ? 0.5f * (cosf(dd * 0.62831853071795f) + 1.0f) : 0.0f;
            float u = expf(-dd) - means[k];
            ea[bb][k] = cut * expf(-betas[k] * u * u);
        }
        __syncthreads();
        for (int l = 0; l < NL; l++) {
            const float* WfE = Wf + (size_t)l * 160 * GC + 128 * GC;
            const float* WsE = Ws + (size_t)l * 160 * GC + 128 * GC;
            for (int i = tid; i < RBF * GC; i += 256) {
                sw[i] = WfE[i];
                sw[RBF * GC + i] = WsE[i];
            }
            __syncthreads();
            for (int it = tid; it < 65 * GC; it += 256) {
                int bb = it >> 6, c = it & 63;
                float af = 0.0f, as = 0.0f;
                #pragma unroll
                for (int k = 0; k < RBF; k++) {
                    float e_ = ea[bb][k];
                    af = fmaf(e_, sw[k * GC + c], af);
                    as = fmaf(e_, sw[RBF * GC + k * GC + c], as);
                }
                sF[bb][c] = __floats2half2_rn(af * LOG2E, as * LOG2E);
            }
            __syncthreads();
            for (int it = tid; it < 64 * GC; it += 256) {
                int bb = it >> 6, c = it & 63;
                int bin = tb * 64 + bb;
                if (bin < BINS + 2) {
                    float2 f0 = __half22float2(sF[bb][c]);
                    float2 f1 = __half22float2(sF[bb + 1][c]);
                    __half2 t0 = sF[bb][c];
                    __half2 dt = __floats2half2_rn(f1.x - f0.x, f1.y - f0.y);
                    uint2 v;
                    v.x = *reinterpret_cast<uint32_t*>(&t0);
                    v.y = *reinterpret_cast<uint32_t*>(&dt);
                    g_tab[((size_t)l * (BINS + 2) + bin) * GC + c] = v;
                }
            }
            __syncthreads();
        }
    } else {
        int nb = bid - GE - GT;
        int c = tid & 63, g = tid >> 6;
        float bc = preb[c];
        for (int n = nb * 4 + g; n < NN; n += GN * 4) {
            const float* er = &emb[atom[n] * NF];
            float acc = bc;
            #pragma unroll 4
            for (int f = 0; f < NF; f++)
                acc = fmaf(__ldg(&er[f]), preW[f * GC + c], acc);
            g_x[(size_t)n * GC + c] = fmaxf(acc, 0.0f);
        }
    }
}

// ---------------- launch 2: shfl scan (+ invdeg = ln2/deg) ----------------
__global__ void scan_kernel()
{
    __shared__ int wsum[32];
    __shared__ int wexcl[32];
    __shared__ int stotal;
    int tid = threadIdx.x, lane = tid & 31, wid = tid >> 5;
    int carry = 0;
    for (int base = 0; base < NN; base += 4096) {
        int i0 = base + tid * 4;
        int a0 = (i0 + 0 < NN) ? g_deg[i0 + 0] : 0;
        int a1 = (i0 + 1 < NN) ? g_deg[i0 + 1] : 0;
        int a2 = (i0 + 2 < NN) ? g_deg[i0 + 2] : 0;
        int a3 = (i0 + 3 < NN) ? g_deg[i0 + 3] : 0;
        int s0 = a0, s1 = s0 + a1, s2 = s1 + a2, s3 = s2 + a3;
        int inc = s3;
        #pragma unroll
        for (int off = 1; off < 32; off <<= 1) {
            int t = __shfl_up_sync(0xffffffffu, inc, off);
            if (lane >= off) inc += t;
        }
        if (lane == 31) wsum[wid] = inc;
        __syncthreads();
        if (wid == 0) {
            int w = wsum[lane];
            int wi = w;
            #pragma unroll
            for (int off = 1; off < 32; off <<= 1) {
                int t = __shfl_up_sync(0xffffffffu, wi, off);
                if (lane >= off) wi += t;
            }
            wexcl[lane] = wi - w;
            if (lane == 31) stotal = wi;
        }
        __syncthreads();
        int excl = carry + wexcl[wid] + (inc - s3);
        if (i0 + 0 < NN) { g_rowptr[i0 + 0] = excl;      g_wofs[i0 + 0] = excl;
                           g_invdeg[i0 + 0] = a0 > 0 ? LN2 / (float)a0 : 0.0f; }
        if (i0 + 1 < NN) { g_rowptr[i0 + 1] = excl + s0; g_wofs[i0 + 1] = excl + s0;
                           g_invdeg[i0 + 1] = a1 > 0 ? LN2 / (float)a1 : 0.0f; }
        if (i0 + 2 < NN) { g_rowptr[i0 + 2] = excl + s1; g_wofs[i0 + 2] = excl + s1;
                           g_invdeg[i0 + 2] = a2 > 0 ? LN2 / (float)a2 : 0.0f; }
        if (i0 + 3 < NN) { g_rowptr[i0 + 3] = excl + s2; g_wofs[i0 + 3] = excl + s2;
                           g_invdeg[i0 + 3] = a3 > 0 ? LN2 / (float)a3 : 0.0f; }
        carry += stotal;
        __syncthreads();
    }
}

// ---------------- per-layer proj (+ one-time meta build, stats-zero, BN-on-read) ----------------
#define PROJ_SMEM ((4 * 64 * 64 + 32 * 64) * 4)
__global__ __launch_bounds__(256) void proj_kernel(const float* __restrict__ Wf_l,
                                                   const float* __restrict__ Ws_l,
                                                   const int* __restrict__ src,
                                                   const int* __restrict__ dst,
                                                   int do_permute,
                                                   const float* __restrict__ stats_prev,
                                                   const float* __restrict__ gamma_prev,
                                                   const float* __restrict__ beta_prev,
                                                   int apply_bn, int zero_parity)
{
    if (blockIdx.x == 0 && threadIdx.x < 128)
        g_stats[zero_parity * 128 + threadIdx.x] = 0.0f;

    if (do_permute) {
        for (int e = blockIdx.x * blockDim.x + threadIdx.x; e < NE;
             e += gridDim.x * blockDim.x) {
            int d = dst[e];
            int p = atomicAdd(&g_wofs[d], 1);
            float t = g_t[e];
            int b = (int)t;
            __half2 fr2 = __half2half2(__float2half_rn(t - (float)b));
            g_meta[p] = make_int4(src[e] * 256, b * 512,
                                  (int)*reinterpret_cast<uint32_t*>(&fr2), 0);
        }
    }

    extern __shared__ float sm[];
    float4* wsm4 = (float4*)sm;                    // [64][64] float4 (Af,As,Bf,Bs weights, log2e-scaled)
    float*  xs   = sm + 4 * 64 * 64;               // [32][64]
    float4* xs4  = (float4*)xs;
    __shared__ float ksc[64], ksh[64];

    if (threadIdx.x < 64) {
        float s = 1.0f, t = 0.0f;
        if (apply_bn) {
            const float invN = 1.0f / (float)NN;
            float mu = stats_prev[threadIdx.x] * invN;
            float var = stats_prev[64 + threadIdx.x] * invN - mu * mu;
            s = rsqrtf(var + 1e-5f) * gamma_prev[threadIdx.x];
            t = beta_prev[threadIdx.x] - mu * s;
        }
        ksc[threadIdx.x] = s;
        ksh[threadIdx.x] = t;
    }

    for (int i = threadIdx.x; i < 64 * 64; i += blockDim.x) {
        int k = i >> 6, c = i & 63;
        wsm4[i] = make_float4(Wf_l[k * GC + c] * LOG2E,
                              Ws_l[k * GC + c] * LOG2E,
                              Wf_l[(64 + k) * GC + c] * LOG2E,
                              Ws_l[(64 + k) * GC + c] * LOG2E);
    }

    int c = threadIdx.x & 63;
    int g = threadIdx.x >> 6;

    for (int nb = blockIdx.x * 32; nb < NN; nb += gridDim.x * 32) {
        __syncthreads();
        for (int i = threadIdx.x; i < 32 * 64; i += blockDim.x) {
            int nn = nb + (i >> 6);
            int cc = i & 63;
            xs[i] = (nn < NN)
                  ? fmaf(g_x[(size_t)nn * GC + cc], ksc[cc], ksh[cc]) : 0.0f;
        }
        __syncthreads();

        float acc[8][4] = {};
        #pragma unroll
        for (int k4 = 0; k4 < 16; k4++) {
            float4 wA = wsm4[(4 * k4 + 0) * 64 + c];
            float4 wB = wsm4[(4 * k4 + 1) * 64 + c];
            float4 wC = wsm4[(4 * k4 + 2) * 64 + c];
            float4 wD = wsm4[(4 * k4 + 3) * 64 + c];
            #pragma unroll
            for (int j = 0; j < 8; j++) {
                float4 xv = xs4[(g * 8 + j) * 16 + k4];
                acc[j][0] = fmaf(xv.x, wA.x, fmaf(xv.y, wB.x, fmaf(xv.z, wC.x, fmaf(xv.w, wD.x, acc[j][0]))));
                acc[j][1] = fmaf(xv.x, wA.y, fmaf(xv.y, wB.y, fmaf(xv.z, wC.y, fmaf(xv.w, wD.y, acc[j][1]))));
                acc[j][2] = fmaf(xv.x, wA.z, fmaf(xv.y, wB.z, fmaf(xv.z, wC.z, fmaf(xv.w, wD.z, acc[j][2]))));
                acc[j][3] = fmaf(xv.x, wA.w, fmaf(xv.y, wB.w, fmaf(xv.z, wC.w, fmaf(xv.w, wD.w, acc[j][3]))));
            }
        }
        #pragma unroll
        for (int j = 0; j < 8; j++) {
            int n = nb + g * 8 + j;
            if (n < NN) {
                g_projA[(size_t)n * GC + c] = make_float2(acc[j][0], acc[j][1]);
                g_projB[(size_t)n * GC + c] = __floats2half2_rn(acc[j][2], acc[j][3]);
            }
        }
    }
}

// ---------------- fused CSR message + aggregate + residual + BN stats ----------------
__global__ __launch_bounds__(256) void msg_kernel(const char* __restrict__ tabL,
                                                  const float* __restrict__ bfv,
                                                  const float* __restrict__ bsv,
                                                  const float* __restrict__ stats_prev,
                                                  const float* __restrict__ gamma_prev,
                                                  const float* __restrict__ beta_prev,
                                                  int apply_bn,
                                                  float* __restrict__ stats_out)
{
    int c = threadIdx.x & 63;
    int g = threadIdx.x >> 6;
    float bfc = bfv[c] * LOG2E, bsc = bsv[c] * LOG2E;

    float kscale = 1.0f, kshift = 0.0f;
    if (apply_bn) {
        const float invN = 1.0f / (float)NN;
        float mu = stats_prev[c] * invN;
        float var = stats_prev[64 + c] * invN - mu * mu;
        kscale = rsqrtf(var + 1e-5f) * gamma_prev[c];
        kshift = beta_prev[c] - mu * kscale;
    }

    const char* pB = (const char*)g_projB + (c << 2);
    const char* pT = tabL + (c << 3);

    float lsum = 0.0f, lsq = 0.0f;

    for (int n = blockIdx.x * 4 + g; n < NN; n += gridDim.x * 4) {
        int start = g_rowptr[n];
        int deg = g_deg[n];
        float2 A = __ldg(&g_projA[(size_t)n * GC + c]);
        float negb = -(bfc + A.x);
        float bases = bsc + A.y;
        float invd = __ldg(&g_invdeg[n]);   // ln2/deg
        float acc = 0.0f;

        #pragma unroll 2
        for (int i = 0; i < deg; i++) {
            int4 m = __ldg(&g_meta[start + i]);
            __half2 fr2 = *reinterpret_cast<__half2*>(&m.z);
            __half2 B = __ldg((const __half2*)(pB + m.x));
            uint2 r = __ldg((const uint2*)(pT + m.y));
            __half2 T0 = *reinterpret_cast<__half2*>(&r.x);
            __half2 dT = *reinterpret_cast<__half2*>(&r.y);
            __half2 BT = __hadd2(B, __hfma2(fr2, dT, T0));
            float2 bt = __half22float2(BT);
            float negf = negb - bt.x;              // -(f*log2e)
            float sv = bases + bt.y;               // s*log2e
            float sig = fast_rcp(1.0f + fast_ex2(negf));
            float lg = fast_lg2(1.0f + fast_ex2(sv));
            float sp = (sv > 28.8539f) ? sv : lg;  // softplus/ln2
            acc = fmaf(sig, sp, acc);
        }

        size_t xi = (size_t)n * GC + c;
        float v = fmaf(g_x[xi], kscale, kshift) + acc * invd;
        g_x[xi] = v;
        lsum += v;
        lsq = fmaf(v, v, lsq);
    }

    __shared__ float ssum[256], ssq[256];
    ssum[threadIdx.x] = lsum;
    ssq[threadIdx.x] = lsq;
    __syncthreads();
    if (g == 0) {
        float a = ssum[c] + ssum[64 + c] + ssum[128 + c] + ssum[192 + c];
        float b = ssq[c] + ssq[64 + c] + ssq[128 + c] + ssq[192 + c];
        atomicAdd(&stats_out[c], a);
        atomicAdd(&stats_out[GC + c], b);
    }
}

// ---------------- final BN normalize (+ deg re-zero for graph replay) ----------------
__global__ __launch_bounds__(256) void bn_norm_kernel(const float* __restrict__ stats,
                                                      const float* __restrict__ gamma,
                                                      const float* __restrict__ beta,
                                                      float* __restrict__ out)
{
    int c = threadIdx.x & 63;
    const float invN = 1.0f / (float)NN;
    float mu = stats[c] * invN;
    float var = stats[GC + c] * invN - mu * mu;
    float scale = rsqrtf(var + 1e-5f) * gamma[c];
    float shift = beta[c] - mu * scale;
    for (int i = blockIdx.x * blockDim.x + threadIdx.x; i < NN * GC;
         i += gridDim.x * blockDim.x) {
        out[i] = fmaf(g_x[i], scale, shift);
    }
    for (int i = blockIdx.x * blockDim.x + threadIdx.x; i < NN;
         i += gridDim.x * blockDim.x)
        g_deg[i] = 0;
}

// ---------------- launch ----------------
extern "C" void kernel_launch(void* const* d_in, const int* in_sizes, int n_in,
                              void* d_out, int out_size)
{
    const int*   atom   = (const int*)d_in[0];
    const float* pos    = (const float*)d_in[1];
    const int*   eidx   = (const int*)d_in[2];
    const float* emb    = (const float*)d_in[3];
    const float* pre_W  = (const float*)d_in[4];
    const float* pre_b  = (const float*)d_in[5];
    const float* Wf     = (const float*)d_in[6];
    const float* bf     = (const float*)d_in[7];
    const float* Ws     = (const float*)d_in[8];
    const float* bs     = (const float*)d_in[9];
    const float* gamma  = (const float*)d_in[10];
    const float* beta   = (const float*)d_in[11];
    const float* means  = (const float*)d_in[12];
    const float* betas  = (const float*)d_in[13];

    const int* src = eidx;
    const int* dst = eidx + NE;

    cudaFuncSetAttribute(proj_kernel, cudaFuncAttributeMaxDynamicSharedMemorySize, PROJ_SMEM);

    void* p_tab = nullptr;
    cudaGetSymbolAddress(&p_tab, g_tab);
    void* p_stats = nullptr;
    cudaGetSymbolAddress(&p_stats, g_stats);
    float* stats = (float*)p_stats;

    prep_kernel<<<GE + GT + GN, 256>>>(pos, src, dst, means, betas,
                                       atom, emb, pre_W, pre_b, Wf, Ws);   // L1
    scan_kernel<<<1, 1024>>>();                                            // L2

    for (int l = 0; l < NL; l++) {
        const float* Wf_l = Wf + (size_t)l * 160 * GC;
        const float* Ws_l = Ws + (size_t)l * 160 * GC;
        const char* tabL = (const char*)p_tab + (size_t)l * (BINS + 2) * GC * 8;
        const float* sprev = stats + ((l - 1) & 1) * 128;
        float* sout = stats + (l & 1) * 128;
        int apply = (l > 0) ? 1 : 0;
        const float* gprev = gamma + (l - 1) * GC;
        const float* bprev = beta + (l - 1) * GC;
        proj_kernel<<<444, 256, PROJ_SMEM>>>(Wf_l, Ws_l, src, dst, (l == 0) ? 1 : 0,
                                             sprev, gprev, bprev, apply, l & 1);
        msg_kernel<<<2048, 256>>>(tabL, bf + l * GC, bs + l * GC,
                                  sprev, gprev, bprev, apply, sout);       // slot 4 on l==0
    }
    bn_norm_kernel<<<888, 256>>>(stats + ((NL - 1) & 1) * 128,
                                 gamma + (NL - 1) * GC, beta + (NL - 1) * GC,
                                 (float*)d_out);
}

// round 7
// speedup vs baseline: 4.5968x; 1.1401x over previous
#include <cuda_runtime.h>
#include <cuda_fp16.h>
#include <math.h>
#include <stdint.h>

#define NN 100000
#define NE 1200000
#define GC 64
#define RBF 32
#define NL 4
#define NF 92
#define BINS 8192
#define LOG2E 1.44269504088896f
#define LN2 0.69314718055995f

// ---------------- scratch ----------------
__device__ float2  g_projA[(size_t)NN * GC];            // (Af',As') fp32 (log2e-scaled)
__device__ __half2 g_projB[(size_t)NN * GC];            // (Bf',Bs') fp16
__device__ float   g_x[(size_t)NN * GC];                // raw (pre-BN) features
__device__ int     g_deg[NN];                           // zero-init; re-zeroed by final bn
__device__ int     g_rowptr[NN];
__device__ int     g_wofs[NN];
__device__ float   g_invdeg[NN];                        // ln2/deg
__device__ float   g_t[NE];
__device__ int4    g_meta[NE];                          // (src*256, bin*512, half2(fr,fr), 0)
__device__ uint2   g_tab[(size_t)NL * (BINS + 2) * GC]; // {half2(T0f,T0s), half2(dTf,dTs)} log2e-scaled
__device__ float   g_stats[2 * 128];

#define GE 2048
#define GT 129
#define GN 1024

typedef unsigned long long u64;

__device__ __forceinline__ float fast_ex2(float x){ float r; asm("ex2.approx.f32 %0,%1;":"=f"(r):"f"(x)); return r; }
__device__ __forceinline__ float fast_lg2(float x){ float r; asm("lg2.approx.f32 %0,%1;":"=f"(r):"f"(x)); return r; }
__device__ __forceinline__ float fast_rcp(float x){ float r; asm("rcp.approx.f32 %0,%1;":"=f"(r):"f"(x)); return r; }
__device__ __forceinline__ u64 ffma2(u64 a, u64 b, u64 c){
    u64 d; asm("fma.rn.f32x2 %0,%1,%2,%3;":"=l"(d):"l"(a),"l"(b),"l"(c)); return d;
}
__device__ __forceinline__ u64 pack2(float lo, float hi){
    u64 d; asm("mov.b64 %0,{%1,%2};":"=l"(d):"f"(lo),"f"(hi)); return d;
}
__device__ __forceinline__ float2 unpack2(u64 v){
    float lo, hi; asm("mov.b64 {%0,%1},%2;":"=f"(lo),"=f"(hi):"l"(v));
    return make_float2(lo, hi);
}

// ---------------- launch 1: edge prep + RBF pair-tables + node init (fused) ----------------
__global__ __launch_bounds__(256) void prep_kernel(const float* __restrict__ pos,
                                                   const int* __restrict__ src,
                                                   const int* __restrict__ dst,
                                                   const float* __restrict__ means,
                                                   const float* __restrict__ betas,
                                                   const int* __restrict__ atom,
                                                   const float* __restrict__ emb,
                                                   const float* __restrict__ preW,
                                                   const float* __restrict__ preb,
                                                   const float* __restrict__ Wf,
                                                   const float* __restrict__ Ws)
{
    int bid = blockIdx.x;
    int tid = threadIdx.x;

    if (bid < GE) {
        for (int e = bid * 256 + tid; e < NE; e += GE * 256) {
            int s = src[e], d = dst[e];
            float dx = pos[s * 3 + 0] - pos[d * 3 + 0];
            float dy = pos[s * 3 + 1] - pos[d * 3 + 1];
            float dz = pos[s * 3 + 2] - pos[d * 3 + 2];
            float dist = sqrtf(dx * dx + dy * dy + dz * dz + 1e-12f);
            g_t[e] = fminf(dist, 5.0f) * ((float)BINS / 5.0f);
            atomicAdd(&g_deg[d], 1);
        }
    } else if (bid < GE + GT) {
        int tb = bid - GE;
        __shared__ float ea[65][RBF];
        __shared__ float sw[2 * RBF * GC];
        __shared__ __half2 sF[65][GC];
        for (int i = tid; i < 65 * RBF; i += 256) {
            int bb = i >> 5, k = i & 31;
            float dd = (float)(tb * 64 + bb) * (5.0f / (float)BINS);
            float cut = (dd < 5.0f) ? 0.5f * (cosf(dd * 0.62831853071795f) + 1.0f) : 0.0f;
            float u = expf(-dd) - means[k];
            ea[bb][k] = cut * expf(-betas[k] * u * u);
        }
        __syncthreads();
        for (int l = 0; l < NL; l++) {
            const float* WfE = Wf + (size_t)l * 160 * GC + 128 * GC;
            const float* WsE = Ws + (size_t)l * 160 * GC + 128 * GC;
            for (int i = tid; i < RBF * GC; i += 256) {
                sw[i] = WfE[i];
                sw[RBF * GC + i] = WsE[i];
            }
            __syncthreads();
            for (int it = tid; it < 65 * GC; it += 256) {
                int bb = it >> 6, c = it & 63;
                float af = 0.0f, as = 0.0f;
                #pragma unroll
                for (int k = 0; k < RBF; k++) {
                    float e_ = ea[bb][k];
                    af = fmaf(e_, sw[k * GC + c], af);
                    as = fmaf(e_, sw[RBF * GC + k * GC + c], as);
                }
                sF[bb][c] = __floats2half2_rn(af * LOG2E, as * LOG2E);
            }
            __syncthreads();
            for (int it = tid; it < 64 * GC; it += 256) {
                int bb = it >> 6, c = it & 63;
                int bin = tb * 64 + bb;
                if (bin < BINS + 2) {
                    float2 f0 = __half22float2(sF[bb][c]);
                    float2 f1 = __half22float2(sF[bb + 1][c]);
                    __half2 t0 = sF[bb][c];
                    __half2 dt = __floats2half2_rn(f1.x - f0.x, f1.y - f0.y);
                    uint2 v;
                    v.x = *reinterpret_cast<uint32_t*>(&t0);
                    v.y = *reinterpret_cast<uint32_t*>(&dt);
                    g_tab[((size_t)l * (BINS + 2) + bin) * GC + c] = v;
                }
            }
            __syncthreads();
        }
    } else {
        int nb = bid - GE - GT;
        int c = tid & 63, g = tid >> 6;
        float bc = preb[c];
        for (int n = nb * 4 + g; n < NN; n += GN * 4) {
            const float* er = &emb[atom[n] * NF];
            float acc = bc;
            #pragma unroll 4
            for (int f = 0; f < NF; f++)
                acc = fmaf(__ldg(&er[f]), preW[f * GC + c], acc);
            g_x[(size_t)n * GC + c] = fmaxf(acc, 0.0f);
        }
    }
}

// ---------------- launch 2: shfl scan (+ invdeg = ln2/deg) ----------------
__global__ void scan_kernel()
{
    __shared__ int wsum[32];
    __shared__ int wexcl[32];
    __shared__ int stotal;
    int tid = threadIdx.x, lane = tid & 31, wid = tid >> 5;
    int carry = 0;
    for (int base = 0; base < NN; base += 4096) {
        int i0 = base + tid * 4;
        int a0 = (i0 + 0 < NN) ? g_deg[i0 + 0] : 0;
        int a1 = (i0 + 1 < NN) ? g_deg[i0 + 1] : 0;
        int a2 = (i0 + 2 < NN) ? g_deg[i0 + 2] : 0;
        int a3 = (i0 + 3 < NN) ? g_deg[i0 + 3] : 0;
        int s0 = a0, s1 = s0 + a1, s2 = s1 + a2, s3 = s2 + a3;
        int inc = s3;
        #pragma unroll
        for (int off = 1; off < 32; off <<= 1) {
            int t = __shfl_up_sync(0xffffffffu, inc, off);
            if (lane >= off) inc += t;
        }
        if (lane == 31) wsum[wid] = inc;
        __syncthreads();
        if (wid == 0) {
            int w = wsum[lane];
            int wi = w;
            #pragma unroll
            for (int off = 1; off < 32; off <<= 1) {
                int t = __shfl_up_sync(0xffffffffu, wi, off);
                if (lane >= off) wi += t;
            }
            wexcl[lane] = wi - w;
            if (lane == 31) stotal = wi;
        }
        __syncthreads();
        int excl = carry + wexcl[wid] + (inc - s3);
        if (i0 + 0 < NN) { g_rowptr[i0 + 0] = excl;      g_wofs[i0 + 0] = excl;
                           g_invdeg[i0 + 0] = a0 > 0 ? LN2 / (float)a0 : 0.0f; }
        if (i0 + 1 < NN) { g_rowptr[i0 + 1] = excl + s0; g_wofs[i0 + 1] = excl + s0;
                           g_invdeg[i0 + 1] = a1 > 0 ? LN2 / (float)a1 : 0.0f; }
        if (i0 + 2 < NN) { g_rowptr[i0 + 2] = excl + s1; g_wofs[i0 + 2] = excl + s1;
                           g_invdeg[i0 + 2] = a2 > 0 ? LN2 / (float)a2 : 0.0f; }
        if (i0 + 3 < NN) { g_rowptr[i0 + 3] = excl + s2; g_wofs[i0 + 3] = excl + s2;
                           g_invdeg[i0 + 3] = a3 > 0 ? LN2 / (float)a3 : 0.0f; }
        carry += stotal;
        __syncthreads();
    }
}

// ---------------- per-layer proj: f32x2 packed FMA, transposed x tile ----------------
// smem: weights float4[64k][64c] (log2e-scaled) + xs_t[64k][34] node-major pairs
#define XPAD 34
#define PROJ_SMEM ((4 * 64 * 64 + 64 * XPAD) * 4)
__global__ __launch_bounds__(256) void proj_kernel(const float* __restrict__ Wf_l,
                                                   const float* __restrict__ Ws_l,
                                                   const int* __restrict__ src,
                                                   const int* __restrict__ dst,
                                                   int do_permute,
                                                   const float* __restrict__ stats_prev,
                                                   const float* __restrict__ gamma_prev,
                                                   const float* __restrict__ beta_prev,
                                                   int apply_bn, int zero_parity)
{
    if (blockIdx.x == 0 && threadIdx.x < 128)
        g_stats[zero_parity * 128 + threadIdx.x] = 0.0f;

    if (do_permute) {
        for (int e = blockIdx.x * blockDim.x + threadIdx.x; e < NE;
             e += gridDim.x * blockDim.x) {
            int d = dst[e];
            int p = atomicAdd(&g_wofs[d], 1);
            float t = g_t[e];
            int b = (int)t;
            __half2 fr2 = __half2half2(__float2half_rn(t - (float)b));
            g_meta[p] = make_int4(src[e] * 256, b * 512,
                                  (int)*reinterpret_cast<uint32_t*>(&fr2), 0);
        }
    }

    extern __shared__ float sm[];
    float4* wsm4 = (float4*)sm;                 // [64][64] (Af,As,Bf,Bs)*log2e
    float*  xst  = sm + 4 * 64 * 64;            // [64 k][XPAD] transposed x tile
    __shared__ float ksc[64], ksh[64];

    if (threadIdx.x < 64) {
        float s = 1.0f, t = 0.0f;
        if (apply_bn) {
            const float invN = 1.0f / (float)NN;
            float mu = stats_prev[threadIdx.x] * invN;
            float var = stats_prev[64 + threadIdx.x] * invN - mu * mu;
            s = rsqrtf(var + 1e-5f) * gamma_prev[threadIdx.x];
            t = beta_prev[threadIdx.x] - mu * s;
        }
        ksc[threadIdx.x] = s;
        ksh[threadIdx.x] = t;
    }

    for (int i = threadIdx.x; i < 64 * 64; i += blockDim.x) {
        int k = i >> 6, c = i & 63;
        wsm4[i] = make_float4(Wf_l[k * GC + c] * LOG2E,
                              Ws_l[k * GC + c] * LOG2E,
                              Wf_l[(64 + k) * GC + c] * LOG2E,
                              Ws_l[(64 + k) * GC + c] * LOG2E);
    }

    int c = threadIdx.x & 63;
    int g = threadIdx.x >> 6;   // 4 groups x 8 nodes (4 node-pairs)

    for (int nb = blockIdx.x * 32; nb < NN; nb += gridDim.x * 32) {
        __syncthreads();
        for (int i = threadIdx.x; i < 32 * 64; i += blockDim.x) {
            int j = i >> 6;          // node-in-tile
            int cc = i & 63;         // k index
            int nn = nb + j;
            xst[cc * XPAD + j] = (nn < NN)
                  ? fmaf(g_x[(size_t)nn * GC + cc], ksc[cc], ksh[cc]) : 0.0f;
        }
        __syncthreads();

        u64 acc[4][4];
        #pragma unroll
        for (int p = 0; p < 4; p++)
            #pragma unroll
            for (int o = 0; o < 4; o++)
                acc[p][o] = 0ull;

        #pragma unroll 8
        for (int k = 0; k < 64; k++) {
            float4 w = wsm4[k * 64 + c];
            u64 w0 = pack2(w.x, w.x);
            u64 w1 = pack2(w.y, w.y);
            u64 w2 = pack2(w.z, w.z);
            u64 w3 = pack2(w.w, w.w);
            const u64* xrow = (const u64*)&xst[k * XPAD + g * 8];
            #pragma unroll
            for (int p = 0; p < 4; p++) {
                u64 x2 = xrow[p];
                acc[p][0] = ffma2(x2, w0, acc[p][0]);
                acc[p][1] = ffma2(x2, w1, acc[p][1]);
                acc[p][2] = ffma2(x2, w2, acc[p][2]);
                acc[p][3] = ffma2(x2, w3, acc[p][3]);
            }
        }
        #pragma unroll
        for (int p = 0; p < 4; p++) {
            float2 a0 = unpack2(acc[p][0]);
            float2 a1 = unpack2(acc[p][1]);
            float2 a2 = unpack2(acc[p][2]);
            float2 a3 = unpack2(acc[p][3]);
            int n0 = nb + g * 8 + 2 * p;
            if (n0 < NN) {
                g_projA[(size_t)n0 * GC + c] = make_float2(a0.x, a1.x);
                g_projB[(size_t)n0 * GC + c] = __floats2half2_rn(a2.x, a3.x);
            }
            if (n0 + 1 < NN) {
                g_projA[(size_t)(n0 + 1) * GC + c] = make_float2(a0.y, a1.y);
                g_projB[(size_t)(n0 + 1) * GC + c] = __floats2half2_rn(a2.y, a3.y);
            }
        }
    }
}

// ---------------- fused CSR message: 2 channels/thread, 32 lanes x 8 node-groups ----------------
__global__ __launch_bounds__(256) void msg_kernel(const char* __restrict__ tabL,
                                                  const float* __restrict__ bfv,
                                                  const float* __restrict__ bsv,
                                                  const float* __restrict__ stats_prev,
                                                  const float* __restrict__ gamma_prev,
                                                  const float* __restrict__ beta_prev,
                                                  int apply_bn,
                                                  float* __restrict__ stats_out)
{
    int lane = threadIdx.x & 31;      // channel pair: channels 2*lane, 2*lane+1
    int g = threadIdx.x >> 5;         // 8 node groups
    int c0 = 2 * lane, c1 = 2 * lane + 1;
    float bf0 = bfv[c0] * LOG2E, bf1 = bfv[c1] * LOG2E;
    float bs0 = bsv[c0] * LOG2E, bs1 = bsv[c1] * LOG2E;

    float ks0 = 1.0f, kt0 = 0.0f, ks1 = 1.0f, kt1 = 0.0f;
    if (apply_bn) {
        const float invN = 1.0f / (float)NN;
        float mu0 = stats_prev[c0] * invN;
        float var0 = stats_prev[64 + c0] * invN - mu0 * mu0;
        ks0 = rsqrtf(var0 + 1e-5f) * gamma_prev[c0];
        kt0 = beta_prev[c0] - mu0 * ks0;
        float mu1 = stats_prev[c1] * invN;
        float var1 = stats_prev[64 + c1] * invN - mu1 * mu1;
        ks1 = rsqrtf(var1 + 1e-5f) * gamma_prev[c1];
        kt1 = beta_prev[c1] - mu1 * ks1;
    }

    const char* pB = (const char*)g_projB + (lane << 3);
    const char* pT = tabL + (lane << 4);

    float lsum0 = 0.f, lsq0 = 0.f, lsum1 = 0.f, lsq1 = 0.f;

    for (int n = blockIdx.x * 8 + g; n < NN; n += gridDim.x * 8) {
        int start = g_rowptr[n];
        int deg = g_deg[n];
        float4 A = __ldg((const float4*)&g_projA[(size_t)n * GC + c0]); // Af0,As0,Af1,As1
        float negb0 = -(bf0 + A.x);
        float base_s0 = bs0 + A.y;
        float negb1 = -(bf1 + A.z);
        float base_s1 = bs1 + A.w;
        float invd = __ldg(&g_invdeg[n]);   // ln2/deg
        float acc0 = 0.0f, acc1 = 0.0f;

        #pragma unroll 2
        for (int i = 0; i < deg; i++) {
            int4 m = __ldg(&g_meta[start + i]);                  // broadcast in group
            __half2 fr2 = *reinterpret_cast<__half2*>(&m.z);
            uint2 Bu = __ldg((const uint2*)(pB + m.x));          // {B(c0), B(c1)}
            uint4 r = __ldg((const uint4*)(pT + m.y));           // {T0(c0),dT(c0),T0(c1),dT(c1)}
            __half2 B0 = *reinterpret_cast<__half2*>(&Bu.x);
            __half2 B1 = *reinterpret_cast<__half2*>(&Bu.y);
            __half2 T00 = *reinterpret_cast<__half2*>(&r.x);
            __half2 dT0 = *reinterpret_cast<__half2*>(&r.y);
            __half2 T01 = *reinterpret_cast<__half2*>(&r.z);
            __half2 dT1 = *reinterpret_cast<__half2*>(&r.w);
            float2 bt0 = __half22float2(__hadd2(B0, __hfma2(fr2, dT0, T00)));
            float2 bt1 = __half22float2(__hadd2(B1, __hfma2(fr2, dT1, T01)));
            float negf0 = negb0 - bt0.x;
            float sv0 = base_s0 + bt0.y;
            float negf1 = negb1 - bt1.x;
            float sv1 = base_s1 + bt1.y;
            float sig0 = fast_rcp(1.0f + fast_ex2(negf0));
            float sig1 = fast_rcp(1.0f + fast_ex2(negf1));
            float lg0 = fast_lg2(1.0f + fast_ex2(sv0));
            float lg1 = fast_lg2(1.0f + fast_ex2(sv1));
            float sp0 = (sv0 > 28.8539f) ? sv0 : lg0;
            float sp1 = (sv1 > 28.8539f) ? sv1 : lg1;
            acc0 = fmaf(sig0, sp0, acc0);
            acc1 = fmaf(sig1, sp1, acc1);
        }

        size_t xi = (size_t)n * GC + c0;
        float2* xp = (float2*)&g_x[xi];
        float2 xv = *xp;
        float v0 = fmaf(xv.x, ks0, kt0) + acc0 * invd;
        float v1 = fmaf(xv.y, ks1, kt1) + acc1 * invd;
        *xp = make_float2(v0, v1);
        lsum0 += v0; lsq0 = fmaf(v0, v0, lsq0);
        lsum1 += v1; lsq1 = fmaf(v1, v1, lsq1);
    }

    __shared__ float ssum[2][256], ssq[2][256];
    ssum[0][threadIdx.x] = lsum0; ssq[0][threadIdx.x] = lsq0;
    ssum[1][threadIdx.x] = lsum1; ssq[1][threadIdx.x] = lsq1;
    __syncthreads();
    if (threadIdx.x < 64) {
        int ch = threadIdx.x;
        int part = ch & 1, ln = ch >> 1;
        float a = 0.f, b = 0.f;
        #pragma unroll
        for (int gg = 0; gg < 8; gg++) {
            a += ssum[part][gg * 32 + ln];
            b += ssq[part][gg * 32 + ln];
        }
        atomicAdd(&stats_out[ch], a);
        atomicAdd(&stats_out[GC + ch], b);
    }
}

// ---------------- final BN normalize (+ deg re-zero for graph replay) ----------------
__global__ __launch_bounds__(256) void bn_norm_kernel(const float* __restrict__ stats,
                                                      const float* __restrict__ gamma,
                                                      const float* __restrict__ beta,
                                                      float* __restrict__ out)
{
    int c = threadIdx.x & 63;
    const float invN = 1.0f / (float)NN;
    float mu = stats[c] * invN;
    float var = stats[GC + c] * invN - mu * mu;
    float scale = rsqrtf(var + 1e-5f) * gamma[c];
    float shift = beta[c] - mu * scale;
    for (int i = blockIdx.x * blockDim.x + threadIdx.x; i < NN * GC;
         i += gridDim.x * blockDim.x) {
        out[i] = fmaf(g_x[i], scale, shift);
    }
    for (int i = blockIdx.x * blockDim.x + threadIdx.x; i < NN;
         i += gridDim.x * blockDim.x)
        g_deg[i] = 0;
}

// ---------------- launch ----------------
extern "C" void kernel_launch(void* const* d_in, const int* in_sizes, int n_in,
                              void* d_out, int out_size)
{
    const int*   atom   = (const int*)d_in[0];
    const float* pos    = (const float*)d_in[1];
    const int*   eidx   = (const int*)d_in[2];
    const float* emb    = (const float*)d_in[3];
    const float* pre_W  = (const float*)d_in[4];
    const float* pre_b  = (const float*)d_in[5];
    const float* Wf     = (const float*)d_in[6];
    const float* bf     = (const float*)d_in[7];
    const float* Ws     = (const float*)d_in[8];
    const float* bs     = (const float*)d_in[9];
    const float* gamma  = (const float*)d_in[10];
    const float* beta   = (const float*)d_in[11];
    const float* means  = (const float*)d_in[12];
    const float* betas  = (const float*)d_in[13];

    const int* src = eidx;
    const int* dst = eidx + NE;

    cudaFuncSetAttribute(proj_kernel, cudaFuncAttributeMaxDynamicSharedMemorySize, PROJ_SMEM);

    void* p_tab = nullptr;
    cudaGetSymbolAddress(&p_tab, g_tab);
    void* p_stats = nullptr;
    cudaGetSymbolAddress(&p_stats, g_stats);
    float* stats = (float*)p_stats;

    prep_kernel<<<GE + GT + GN, 256>>>(pos, src, dst, means, betas,
                                       atom, emb, pre_W, pre_b, Wf, Ws);   // L1
    scan_kernel<<<1, 1024>>>();                                            // L2

    for (int l = 0; l < NL; l++) {
        const float* Wf_l = Wf + (size_t)l * 160 * GC;
        const float* Ws_l = Ws + (size_t)l * 160 * GC;
        const char* tabL = (const char*)p_tab + (size_t)l * (BINS + 2) * GC * 8;
        const float* sprev = stats + ((l - 1) & 1) * 128;
        float* sout = stats + (l & 1) * 128;
        int apply = (l > 0) ? 1 : 0;
        const float* gprev = gamma + (l - 1) * GC;
        const float* bprev = beta + (l - 1) * GC;
        proj_kernel<<<444, 256, PROJ_SMEM>>>(Wf_l, Ws_l, src, dst, (l == 0) ? 1 : 0,
                                             sprev, gprev, bprev, apply, l & 1);
        msg_kernel<<<2048, 256>>>(tabL, bf + l * GC, bs + l * GC,
                                  sprev, gprev, bprev, apply, sout);       // slot 4 on l==0
    }
    bn_norm_kernel<<<888, 256>>>(stats + ((NL - 1) & 1) * 128,
                                 gamma + (NL - 1) * GC, beta + (NL - 1) * GC,
                                 (float*)d_out);
}